// round 6
// baseline (speedup 1.0000x reference)
#include <cuda_runtime.h>
#include <cstdint>

// ---------------------------------------------------------------------------
// Problem constants
// ---------------------------------------------------------------------------
#define BS 4
#define LQ 1024
#define EMBED 256
#define NH 8
#define NL 4
#define NP 16
#define HD 32
#define LEN_V 5440

#define OUT_ELEMS   (BS * LQ * EMBED)
#define LOC_OFFSET  (OUT_ELEMS)
#define LOC_ELEMS   (BS * LQ * NH * NL * NP * 2)
#define ATTN_OFFSET (LOC_OFFSET + LOC_ELEMS)

__constant__ int   c_H[NL]      = {64, 32, 16, 8};
__constant__ int   c_W[NL]      = {64, 32, 16, 8};
__constant__ int   c_start[NL]  = {0, 4096, 5120, 5376};
__constant__ float c_invW[NL]   = {1.0f/64, 1.0f/32, 1.0f/16, 1.0f/8};
__constant__ float c_invH[NL]   = {1.0f/64, 1.0f/32, 1.0f/16, 1.0f/8};

__device__ float g_v[BS * LEN_V * EMBED];   // projected value  ~22.3 MB
__device__ float g_mid[BS * LQ * EMBED];    // pre-W_out         4 MB

// ---------------------------------------------------------------------------
// Packed f32x2 helpers (PTX fma.rn.f32x2)
// ---------------------------------------------------------------------------
__device__ __forceinline__ uint64_t pack2(float x, float y) {
    uint64_t r;
    asm("mov.b64 %0, {%1, %2};" : "=l"(r) : "f"(x), "f"(y));
    return r;
}
__device__ __forceinline__ void unpack2(uint64_t v, float& x, float& y) {
    asm("mov.b64 {%0, %1}, %2;" : "=f"(x), "=f"(y) : "l"(v));
}
__device__ __forceinline__ void ffma2(uint64_t& d, uint64_t a, uint64_t b) {
    asm("fma.rn.f32x2 %0, %1, %2, %0;" : "+l"(d) : "l"(a), "l"(b));
}

// ---------------------------------------------------------------------------
// Fused FFMA2 GEMM:  C[M,N] = A[M,K] @ B[K,N] + bias[N]  (+ fused epilogue)
//   TBM=64, BK=16, 256 threads, microtile 4(m) x TN/16(n).
//   MODE 0: plain +bias store
//   MODE 1: (TN=128) sampling-location transform: C = poly(refp) + (val)/norm
//   MODE 2: (TN=64)  row softmax over the 64-col head block
// A smem [k][m], stride 68 (16B-aligned rows, low-conflict transpose stores).
// B smem chunked: 8-float chunks at 10-float stride -> conflict-free LDS.64.
// ---------------------------------------------------------------------------
#define TBM 64
#define TBK 16
#define SA  68

template <int TN, int MODE>
__global__ __launch_bounds__(256) void gemm_fused(
    const float* __restrict__ A, const float* __restrict__ B,
    const float* __restrict__ bias, float* __restrict__ C,
    const float* __restrict__ refp, int M, int N, int K)
{
    constexpr int NCH  = TN / 8;        // 8-float chunks per k-row
    constexpr int SB   = NCH * 10;      // B row stride (floats)
    constexpr int NT   = TN / 16;       // n cols per thread (8 or 4)
    constexpr int NP2  = NT / 2;        // f32x2 pairs per m (4 or 2)
    constexpr int NB4  = TN / 64;       // B float4 loads per thread (2 or 1)
    constexpr int ND4  = TN / 4;        // float4 per B k-row

    __shared__ float As[2][TBK * SA];
    __shared__ float Bs[2][TBK * SB];

    const int tid = threadIdx.x;
    const int tx  = tid & 15;
    const int ty  = tid >> 4;
    const int m0  = blockIdx.y * TBM;
    const int n0  = blockIdx.x * TN;

    // ---- staging helpers ----
    auto stage_a = [&](int buf, float4 v) {
        int m = tid >> 2, kq = tid & 3;
        float* p = &As[buf][(kq * 4) * SA + m];
        p[0 * SA] = v.x; p[1 * SA] = v.y; p[2 * SA] = v.z; p[3 * SA] = v.w;
    };
    auto stage_b = [&](int buf, float4 v, int i) {
        int kk = i / ND4;
        int n4 = i % ND4;
        float* p = &Bs[buf][kk * SB + (n4 >> 1) * 10 + (n4 & 1) * 4];
        *(float2*)(p)     = make_float2(v.x, v.y);
        *(float2*)(p + 2) = make_float2(v.z, v.w);
    };

    // ---- prologue ----
    stage_a(0, *(const float4*)(A + (size_t)(m0 + (tid >> 2)) * K + (tid & 3) * 4));
#pragma unroll
    for (int r = 0; r < NB4; r++) {
        int i = tid + r * 256;
        stage_b(0, *(const float4*)(B + (size_t)(i / ND4) * N + n0 + (i % ND4) * 4), i);
    }
    __syncthreads();

    uint64_t acc[4][NP2];
#pragma unroll
    for (int i = 0; i < 4; i++)
#pragma unroll
        for (int j = 0; j < NP2; j++) acc[i][j] = 0ull;

    // per-thread B read base (floats)
    const int bofs = (TN == 128) ? tx * 10 : (tx >> 1) * 10 + (tx & 1) * 4;

    const int KT = K / TBK;
    int cur = 0;

    for (int kt = 0; kt < KT; kt++) {
        float4 pa, pb[NB4];
        if (kt + 1 < KT) {
            const int k0 = (kt + 1) * TBK;
            pa = *(const float4*)(A + (size_t)(m0 + (tid >> 2)) * K + k0 + (tid & 3) * 4);
#pragma unroll
            for (int r = 0; r < NB4; r++) {
                int i = tid + r * 256;
                pb[r] = *(const float4*)(B + (size_t)(k0 + i / ND4) * N + n0 + (i % ND4) * 4);
            }
        }

#pragma unroll
        for (int k = 0; k < TBK; k++) {
            float4 a4 = *(const float4*)&As[cur][k * SA + ty * 4];
            const uint64_t* bp = (const uint64_t*)&Bs[cur][k * SB + bofs];
            uint64_t bd[NP2];
#pragma unroll
            for (int j = 0; j < NP2; j++) bd[j] = bp[j];
            uint64_t ad[4];
            ad[0] = pack2(a4.x, a4.x);
            ad[1] = pack2(a4.y, a4.y);
            ad[2] = pack2(a4.z, a4.z);
            ad[3] = pack2(a4.w, a4.w);
#pragma unroll
            for (int i = 0; i < 4; i++)
#pragma unroll
                for (int j = 0; j < NP2; j++)
                    ffma2(acc[i][j], ad[i], bd[j]);
        }

        if (kt + 1 < KT) {
            const int nxt = cur ^ 1;
            stage_a(nxt, pa);
#pragma unroll
            for (int r = 0; r < NB4; r++) stage_b(nxt, pb[r], tid + r * 256);
            __syncthreads();
            cur = nxt;
        }
    }

    // ---- unpack + bias ----
    float bn[NT];
#pragma unroll
    for (int j = 0; j < NT; j++) bn[j] = __ldg(&bias[n0 + tx * NT + j]);

    float o[4][NT];
#pragma unroll
    for (int i = 0; i < 4; i++) {
#pragma unroll
        for (int j = 0; j < NP2; j++)
            unpack2(acc[i][j], o[i][2 * j], o[i][2 * j + 1]);
#pragma unroll
        for (int j = 0; j < NT; j++) o[i][j] += bn[j];
    }

    if (MODE == 1) {
        // ---- sampling-location epilogue (TN=128: one head block) ----
        // stage refp rows m0..m0+63 (64 x 8 floats) into smem
        __syncthreads();
        float* rps = &As[0][0];
        if (tid < 128) {
            int row = tid >> 1, half = tid & 1;
            *(float4*)(rps + row * 8 + half * 4) =
                *(const float4*)(refp + (size_t)(m0 + row) * 8 + half * 4);
        }
        __syncthreads();

#pragma unroll
        for (int i = 0; i < 4; i++) {
            const float* rp = rps + (ty * 4 + i) * 8;
            float rx0 = rp[0], rx1 = rp[1], rx2 = rp[2], rx3 = rp[3];
            float ry0 = rp[4], ry1 = rp[5], ry2 = rp[6], ry3 = rp[7];
            float res[8];
#pragma unroll
            for (int j = 0; j < 8; j++) {
                int r = tx * 8 + j;           // 0..127 within head block
                int l = r >> 5;
                int p = (r >> 1) & 15;
                int c = r & 1;
                float lam = (float)p * (1.0f / 15.0f);
                float pnt = c ? (((ry0 * lam + ry1) * lam + ry2) * lam + ry3)
                              : (((rx0 * lam + rx1) * lam + rx2) * lam + rx3);
                float inv = c ? c_invH[l] : c_invW[l];
                res[j] = pnt + o[i][j] * inv;
            }
            float* crow = C + (size_t)(m0 + ty * 4 + i) * N + n0 + tx * 8;
            *(float4*)(crow)     = make_float4(res[0], res[1], res[2], res[3]);
            *(float4*)(crow + 4) = make_float4(res[4], res[5], res[6], res[7]);
        }
    } else if (MODE == 2) {
        // ---- softmax epilogue (TN=64: row's 64 cols live in 16 lanes) ----
#pragma unroll
        for (int i = 0; i < 4; i++) {
            float mx = fmaxf(fmaxf(o[i][0], o[i][1]), fmaxf(o[i][2], o[i][3]));
#pragma unroll
            for (int off = 1; off < 16; off <<= 1)
                mx = fmaxf(mx, __shfl_xor_sync(0xFFFFFFFFu, mx, off));
            float e0 = expf(o[i][0] - mx);
            float e1 = expf(o[i][1] - mx);
            float e2 = expf(o[i][2] - mx);
            float e3 = expf(o[i][3] - mx);
            float s = (e0 + e1) + (e2 + e3);
#pragma unroll
            for (int off = 1; off < 16; off <<= 1)
                s += __shfl_xor_sync(0xFFFFFFFFu, s, off);
            float inv = 1.0f / s;
            float* crow = C + (size_t)(m0 + ty * 4 + i) * N + n0 + tx * 4;
            *(float4*)crow = make_float4(e0 * inv, e1 * inv, e2 * inv, e3 * inv);
        }
    } else {
        // ---- plain store ----
#pragma unroll
        for (int i = 0; i < 4; i++) {
            float* crow = C + (size_t)(m0 + ty * 4 + i) * N + n0 + tx * NT;
            if (TN == 128) {
                *(float4*)(crow)     = make_float4(o[i][0], o[i][1], o[i][2], o[i][3]);
                *(float4*)(crow + 4) = make_float4(o[i][4], o[i][5], o[i][6], o[i][7]);
            } else {
                *(float4*)(crow)     = make_float4(o[i][0], o[i][1], o[i][2], o[i][3]);
            }
        }
    }
}

// ---------------------------------------------------------------------------
// Gather kernel: warp per (b,q,h); lane = (corner, channel-group).
// ---------------------------------------------------------------------------
__global__ __launch_bounds__(256) void gather_kernel(
    const float* __restrict__ v,
    const float* __restrict__ loc,
    const float* __restrict__ attn,
    float* __restrict__ out)
{
    const int bq = blockIdx.x;
    const int b = bq >> 10;
    const int h = threadIdx.x >> 5;
    const int lane = threadIdx.x & 31;
    const int corner = lane >> 3;
    const int cg = lane & 7;
    const int dx = corner & 1;
    const int dy = corner >> 1;

    const float* lh = loc  + ((size_t)bq * NH + h) * (NL * NP * 2);
    const float* ah = attn + ((size_t)bq * NH + h) * (NL * NP);
    const float* vb = v + (size_t)b * LEN_V * EMBED + h * HD + cg * 4;

    float4 acc = make_float4(0.f, 0.f, 0.f, 0.f);

#pragma unroll
    for (int lvl = 0; lvl < NL; lvl++) {
        const int W = c_W[lvl];
        const int H = c_H[lvl];
        const float* vl = vb + (size_t)c_start[lvl] * EMBED;
        const float fW = (float)W, fH = (float)H;

#pragma unroll 4
        for (int p = 0; p < NP; p++) {
            int sp = lvl * NP + p;
            float lx = __ldg(&lh[sp * 2 + 0]);
            float ly = __ldg(&lh[sp * 2 + 1]);
            float a  = __ldg(&ah[sp]);

            float x = lx * fW - 0.5f;
            float y = ly * fH - 0.5f;
            float x0f = floorf(x);
            float y0f = floorf(y);
            float wx = x - x0f;
            float wy = y - y0f;
            int xi = (int)x0f + dx;
            int yi = (int)y0f + dy;

            bool valid = (xi >= 0) & (xi < W) & (yi >= 0) & (yi < H);
            float wcx = dx ? wx : (1.0f - wx);
            float wcy = dy ? wy : (1.0f - wy);
            float w = valid ? (wcx * wcy * a) : 0.0f;

            if (w != 0.0f) {
                int cx = min(max(xi, 0), W - 1);
                int cy = min(max(yi, 0), H - 1);
                float4 vv = *(const float4*)(vl + (size_t)(cy * W + cx) * EMBED);
                acc.x = fmaf(w, vv.x, acc.x);
                acc.y = fmaf(w, vv.y, acc.y);
                acc.z = fmaf(w, vv.z, acc.z);
                acc.w = fmaf(w, vv.w, acc.w);
            }
        }
    }

#pragma unroll
    for (int off = 8; off <= 16; off <<= 1) {
        acc.x += __shfl_xor_sync(0xFFFFFFFFu, acc.x, off);
        acc.y += __shfl_xor_sync(0xFFFFFFFFu, acc.y, off);
        acc.z += __shfl_xor_sync(0xFFFFFFFFu, acc.z, off);
        acc.w += __shfl_xor_sync(0xFFFFFFFFu, acc.w, off);
    }

    if (lane < 8) {
        float* orow = out + ((size_t)bq * NH + h) * HD + cg * 4;
        *(float4*)orow = acc;
    }
}

// ---------------------------------------------------------------------------
// Launch
// ---------------------------------------------------------------------------
extern "C" void kernel_launch(void* const* d_in, const int* in_sizes, int n_in,
                              void* d_out, int out_size)
{
    const float* query  = (const float*)d_in[0];
    const float* refp   = (const float*)d_in[1];
    const float* value  = (const float*)d_in[2];
    const float* W_val  = (const float*)d_in[3];
    const float* b_val  = (const float*)d_in[4];
    const float* W_off  = (const float*)d_in[5];
    const float* b_off  = (const float*)d_in[6];
    const float* W_attn = (const float*)d_in[7];
    const float* b_attn = (const float*)d_in[8];
    const float* W_out  = (const float*)d_in[9];
    const float* b_out  = (const float*)d_in[10];

    float* out  = (float*)d_out;
    float* loc  = out + LOC_OFFSET;
    float* attn = out + ATTN_OFFSET;

    float* gv;
    float* gmid;
    cudaGetSymbolAddress((void**)&gv, g_v);
    cudaGetSymbolAddress((void**)&gmid, g_mid);

    // 1. sampling offsets + fused location transform -> loc region [4096,1024]
    {
        dim3 grid(1024 / 128, (BS * LQ) / TBM);      // 8 x 64 = 512 CTAs
        gemm_fused<128, 1><<<grid, 256>>>(query, W_off, b_off, loc, refp,
                                          BS * LQ, 1024, EMBED);
    }
    // 2. attn logits + fused softmax -> attn region [4096,512]
    {
        dim3 grid(512 / 64, (BS * LQ) / TBM);        // 8 x 64 = 512 CTAs
        gemm_fused<64, 2><<<grid, 256>>>(query, W_attn, b_attn, attn, nullptr,
                                         BS * LQ, 512, EMBED);
    }
    // 3. value projection [21760,256]
    {
        dim3 grid(EMBED / 128, (BS * LEN_V) / TBM);  // 2 x 340 = 680 CTAs
        gemm_fused<128, 0><<<grid, 256>>>(value, W_val, b_val, gv, nullptr,
                                          BS * LEN_V, EMBED, EMBED);
    }
    // 4. bilinear gather + attention-weighted sum
    gather_kernel<<<BS * LQ, 256>>>(gv, loc, attn, gmid);

    // 5. output projection [4096,256]
    {
        dim3 grid(EMBED / 128, (BS * LQ) / TBM);     // 2 x 64 = 128 CTAs
        gemm_fused<128, 0><<<grid, 256>>>(gmid, W_out, b_out, out, nullptr,
                                          BS * LQ, EMBED, EMBED);
    }
}

// round 7
// speedup vs baseline: 1.0161x; 1.0161x over previous
#include <cuda_runtime.h>
#include <cstdint>

// ---------------------------------------------------------------------------
// Problem constants
// ---------------------------------------------------------------------------
#define BS 4
#define LQ 1024
#define EMBED 256
#define NH 8
#define NL 4
#define NP 16
#define HD 32
#define LEN_V 5440

#define OUT_ELEMS   (BS * LQ * EMBED)
#define LOC_OFFSET  (OUT_ELEMS)
#define LOC_ELEMS   (BS * LQ * NH * NL * NP * 2)
#define ATTN_OFFSET (LOC_OFFSET + LOC_ELEMS)

__constant__ int   c_H[NL]      = {64, 32, 16, 8};
__constant__ int   c_W[NL]      = {64, 32, 16, 8};
__constant__ int   c_start[NL]  = {0, 4096, 5120, 5376};
__constant__ float c_invW[NL]   = {1.0f/64, 1.0f/32, 1.0f/16, 1.0f/8};
__constant__ float c_invH[NL]   = {1.0f/64, 1.0f/32, 1.0f/16, 1.0f/8};

__device__ float  g_v[BS * LEN_V * EMBED];            // projected value ~22.3 MB
__device__ float  g_mid[BS * LQ * EMBED];             // pre-W_out        4 MB
// per (bq,h,sample,corner): {idx_as_float, weight}   ~67 MB
__device__ float2 g_meta[BS * LQ * NH * NL * NP * 4];

// ---------------------------------------------------------------------------
// Packed f32x2 helpers
// ---------------------------------------------------------------------------
__device__ __forceinline__ uint64_t pack2(float x, float y) {
    uint64_t r;
    asm("mov.b64 %0, {%1, %2};" : "=l"(r) : "f"(x), "f"(y));
    return r;
}
__device__ __forceinline__ void unpack2(uint64_t v, float& x, float& y) {
    asm("mov.b64 {%0, %1}, %2;" : "=f"(x), "=f"(y) : "l"(v));
}
__device__ __forceinline__ void ffma2(uint64_t& d, uint64_t a, uint64_t b) {
    asm("fma.rn.f32x2 %0, %1, %2, %0;" : "+l"(d) : "l"(a), "l"(b));
}

// ---------------------------------------------------------------------------
// Fused FFMA2 GEMM:  C[M,N] = A[M,K] @ B[K,N] + bias[N]  (+ fused epilogue)
//   TBM=64, BK=16, 256 threads, microtile 4(m) x TN/16(n).
//   MODE 0: plain +bias store
//   MODE 1: (TN=128) sampling-location transform + gather-meta precompute
//   MODE 2: (TN=64)  row softmax over the 64-col head block
// ---------------------------------------------------------------------------
#define TBM 64
#define TBK 16
#define SA  68

template <int TN, int MODE>
__global__ __launch_bounds__(256) void gemm_fused(
    const float* __restrict__ A, const float* __restrict__ B,
    const float* __restrict__ bias, float* __restrict__ C,
    const float* __restrict__ refp, float2* __restrict__ meta,
    int M, int N, int K)
{
    constexpr int NCH  = TN / 8;
    constexpr int SB   = NCH * 10;
    constexpr int NT   = TN / 16;
    constexpr int NP2  = NT / 2;
    constexpr int NB4  = TN / 64;
    constexpr int ND4  = TN / 4;

    __shared__ float As[2][TBK * SA];
    __shared__ float Bs[2][TBK * SB];

    const int tid = threadIdx.x;
    const int tx  = tid & 15;
    const int ty  = tid >> 4;
    const int m0  = blockIdx.y * TBM;
    const int n0  = blockIdx.x * TN;

    auto stage_a = [&](int buf, float4 v) {
        int m = tid >> 2, kq = tid & 3;
        float* p = &As[buf][(kq * 4) * SA + m];
        p[0 * SA] = v.x; p[1 * SA] = v.y; p[2 * SA] = v.z; p[3 * SA] = v.w;
    };
    auto stage_b = [&](int buf, float4 v, int i) {
        int kk = i / ND4;
        int n4 = i % ND4;
        float* p = &Bs[buf][kk * SB + (n4 >> 1) * 10 + (n4 & 1) * 4];
        *(float2*)(p)     = make_float2(v.x, v.y);
        *(float2*)(p + 2) = make_float2(v.z, v.w);
    };

    stage_a(0, *(const float4*)(A + (size_t)(m0 + (tid >> 2)) * K + (tid & 3) * 4));
#pragma unroll
    for (int r = 0; r < NB4; r++) {
        int i = tid + r * 256;
        stage_b(0, *(const float4*)(B + (size_t)(i / ND4) * N + n0 + (i % ND4) * 4), i);
    }
    __syncthreads();

    uint64_t acc[4][NP2];
#pragma unroll
    for (int i = 0; i < 4; i++)
#pragma unroll
        for (int j = 0; j < NP2; j++) acc[i][j] = 0ull;

    const int bofs = (TN == 128) ? tx * 10 : (tx >> 1) * 10 + (tx & 1) * 4;
    const int KT = K / TBK;
    int cur = 0;

    for (int kt = 0; kt < KT; kt++) {
        float4 pa, pb[NB4];
        if (kt + 1 < KT) {
            const int k0 = (kt + 1) * TBK;
            pa = *(const float4*)(A + (size_t)(m0 + (tid >> 2)) * K + k0 + (tid & 3) * 4);
#pragma unroll
            for (int r = 0; r < NB4; r++) {
                int i = tid + r * 256;
                pb[r] = *(const float4*)(B + (size_t)(k0 + i / ND4) * N + n0 + (i % ND4) * 4);
            }
        }

#pragma unroll
        for (int k = 0; k < TBK; k++) {
            float4 a4 = *(const float4*)&As[cur][k * SA + ty * 4];
            const uint64_t* bp = (const uint64_t*)&Bs[cur][k * SB + bofs];
            uint64_t bd[NP2];
#pragma unroll
            for (int j = 0; j < NP2; j++) bd[j] = bp[j];
            uint64_t ad[4];
            ad[0] = pack2(a4.x, a4.x);
            ad[1] = pack2(a4.y, a4.y);
            ad[2] = pack2(a4.z, a4.z);
            ad[3] = pack2(a4.w, a4.w);
#pragma unroll
            for (int i = 0; i < 4; i++)
#pragma unroll
                for (int j = 0; j < NP2; j++)
                    ffma2(acc[i][j], ad[i], bd[j]);
        }

        if (kt + 1 < KT) {
            const int nxt = cur ^ 1;
            stage_a(nxt, pa);
#pragma unroll
            for (int r = 0; r < NB4; r++) stage_b(nxt, pb[r], tid + r * 256);
            __syncthreads();
            cur = nxt;
        }
    }

    float bn[NT];
#pragma unroll
    for (int j = 0; j < NT; j++) bn[j] = __ldg(&bias[n0 + tx * NT + j]);

    float o[4][NT];
#pragma unroll
    for (int i = 0; i < 4; i++) {
#pragma unroll
        for (int j = 0; j < NP2; j++)
            unpack2(acc[i][j], o[i][2 * j], o[i][2 * j + 1]);
#pragma unroll
        for (int j = 0; j < NT; j++) o[i][j] += bn[j];
    }

    if (MODE == 1) {
        // ---- sampling-location transform + gather-meta precompute ----
        __syncthreads();
        float* rps = &As[0][0];
        if (tid < 128) {
            int row = tid >> 1, half = tid & 1;
            *(float4*)(rps + row * 8 + half * 4) =
                *(const float4*)(refp + (size_t)(m0 + row) * 8 + half * 4);
        }
        __syncthreads();

        const int h = blockIdx.x;              // head block (N=1024, TN=128)
        const int lvl = tx >> 2;               // constant per thread
        const int W = c_W[lvl], H = c_H[lvl];
        const float fW = (float)W, fH = (float)H;
        const float invW = c_invW[lvl], invH = c_invH[lvl];
        const int cstE = c_start[lvl] * EMBED;

#pragma unroll
        for (int i = 0; i < 4; i++) {
            const int bq = m0 + ty * 4 + i;
            const float* rp = rps + (ty * 4 + i) * 8;
            float rx0 = rp[0], rx1 = rp[1], rx2 = rp[2], rx3 = rp[3];
            float ry0 = rp[4], ry1 = rp[5], ry2 = rp[6], ry3 = rp[7];
            float res[8];
#pragma unroll
            for (int j = 0; j < 8; j++) {
                int r = tx * 8 + j;
                int p = (r >> 1) & 15;
                int c = r & 1;
                float lam = (float)p * (1.0f / 15.0f);
                float pnt = c ? (((ry0 * lam + ry1) * lam + ry2) * lam + ry3)
                              : (((rx0 * lam + rx1) * lam + rx2) * lam + rx3);
                float inv = c ? invH : invW;
                res[j] = pnt + o[i][j] * inv;
            }
            // store loc (required output)
            float* crow = C + (size_t)bq * N + n0 + tx * 8;
            *(float4*)(crow)     = make_float4(res[0], res[1], res[2], res[3]);
            *(float4*)(crow + 4) = make_float4(res[4], res[5], res[6], res[7]);

            // gather metadata for the 4 samples this thread owns
            float2* mbase = meta + ((size_t)(bq * NH + h) * 64) * 4;
#pragma unroll
            for (int j = 0; j < 8; j += 2) {
                int p = ((tx * 8 + j) >> 1) & 15;
                int sp = lvl * NP + p;

                float x = res[j]     * fW - 0.5f;
                float y = res[j + 1] * fH - 0.5f;
                float x0f = floorf(x);
                float y0f = floorf(y);
                float wx = x - x0f;
                float wy = y - y0f;
                int x0 = (int)x0f, y0 = (int)y0f;
                int x1 = x0 + 1,   y1 = y0 + 1;

                bool vx0 = (x0 >= 0) & (x0 < W);
                bool vx1 = (x1 >= 0) & (x1 < W);
                bool vy0 = (y0 >= 0) & (y0 < H);
                bool vy1 = (y1 >= 0) & (y1 < H);

                float w00 = (vx0 & vy0) ? (1.0f - wx) * (1.0f - wy) : 0.0f;
                float w10 = (vx1 & vy0) ? wx * (1.0f - wy)          : 0.0f;
                float w01 = (vx0 & vy1) ? (1.0f - wx) * wy          : 0.0f;
                float w11 = (vx1 & vy1) ? wx * wy                   : 0.0f;

                int cx0 = min(max(x0, 0), W - 1);
                int cx1 = min(max(x1, 0), W - 1);
                int cy0 = min(max(y0, 0), H - 1);
                int cy1 = min(max(y1, 0), H - 1);

                int i00 = cstE + (cy0 * W + cx0) * EMBED;
                int i10 = cstE + (cy0 * W + cx1) * EMBED;
                int i01 = cstE + (cy1 * W + cx0) * EMBED;
                int i11 = cstE + (cy1 * W + cx1) * EMBED;

                float4* mp = (float4*)(mbase + sp * 4);
                mp[0] = make_float4(__int_as_float(i00), w00,
                                    __int_as_float(i10), w10);
                mp[1] = make_float4(__int_as_float(i01), w01,
                                    __int_as_float(i11), w11);
            }
        }
    } else if (MODE == 2) {
#pragma unroll
        for (int i = 0; i < 4; i++) {
            float mx = fmaxf(fmaxf(o[i][0], o[i][1]), fmaxf(o[i][2], o[i][3]));
#pragma unroll
            for (int off = 1; off < 16; off <<= 1)
                mx = fmaxf(mx, __shfl_xor_sync(0xFFFFFFFFu, mx, off));
            float e0 = expf(o[i][0] - mx);
            float e1 = expf(o[i][1] - mx);
            float e2 = expf(o[i][2] - mx);
            float e3 = expf(o[i][3] - mx);
            float s = (e0 + e1) + (e2 + e3);
#pragma unroll
            for (int off = 1; off < 16; off <<= 1)
                s += __shfl_xor_sync(0xFFFFFFFFu, s, off);
            float inv = 1.0f / s;
            float* crow = C + (size_t)(m0 + ty * 4 + i) * N + n0 + tx * 4;
            *(float4*)crow = make_float4(e0 * inv, e1 * inv, e2 * inv, e3 * inv);
        }
    } else {
#pragma unroll
        for (int i = 0; i < 4; i++) {
            float* crow = C + (size_t)(m0 + ty * 4 + i) * N + n0 + tx * NT;
            *(float4*)(crow) = make_float4(o[i][0], o[i][1], o[i][2], o[i][3]);
            if (TN == 128)
                *(float4*)(crow + 4) = make_float4(o[i][4], o[i][5], o[i][6], o[i][7]);
        }
    }
}

// ---------------------------------------------------------------------------
// Slim gather: warp per (b,q,h); lane = (corner, channel-group).
// Per sample: meta LDG.64 + attn LDG.32 + FMUL + predicated LDG.128 + 4 FFMA.
// ---------------------------------------------------------------------------
__global__ __launch_bounds__(256) void gather_kernel(
    const float* __restrict__ v,
    const float2* __restrict__ meta,
    const float* __restrict__ attn,
    float* __restrict__ out)
{
    const int bq = blockIdx.x;
    const int b = bq >> 10;
    const int h = threadIdx.x >> 5;
    const int lane = threadIdx.x & 31;
    const int corner = lane >> 3;
    const int cg = lane & 7;

    const float2* mh = meta + ((size_t)(bq * NH + h) * 64) * 4 + corner;
    const float*  ah = attn + ((size_t)bq * NH + h) * 64;
    const float*  vb = v + (size_t)b * LEN_V * EMBED + h * HD + cg * 4;

    float4 acc = make_float4(0.f, 0.f, 0.f, 0.f);

#pragma unroll 4
    for (int sp = 0; sp < 64; sp++) {
        float2 mw = __ldg(&mh[sp * 4]);
        float a = __ldg(&ah[sp]);
        float w = mw.y * a;
        if (w != 0.0f) {
            int idx = __float_as_int(mw.x);
            float4 vv = *(const float4*)(vb + idx);
            acc.x = fmaf(w, vv.x, acc.x);
            acc.y = fmaf(w, vv.y, acc.y);
            acc.z = fmaf(w, vv.z, acc.z);
            acc.w = fmaf(w, vv.w, acc.w);
        }
    }

#pragma unroll
    for (int off = 8; off <= 16; off <<= 1) {
        acc.x += __shfl_xor_sync(0xFFFFFFFFu, acc.x, off);
        acc.y += __shfl_xor_sync(0xFFFFFFFFu, acc.y, off);
        acc.z += __shfl_xor_sync(0xFFFFFFFFu, acc.z, off);
        acc.w += __shfl_xor_sync(0xFFFFFFFFu, acc.w, off);
    }

    if (lane < 8) {
        float* orow = out + ((size_t)bq * NH + h) * HD + cg * 4;
        *(float4*)orow = acc;
    }
}

// ---------------------------------------------------------------------------
// Launch
// ---------------------------------------------------------------------------
extern "C" void kernel_launch(void* const* d_in, const int* in_sizes, int n_in,
                              void* d_out, int out_size)
{
    const float* query  = (const float*)d_in[0];
    const float* refp   = (const float*)d_in[1];
    const float* value  = (const float*)d_in[2];
    const float* W_val  = (const float*)d_in[3];
    const float* b_val  = (const float*)d_in[4];
    const float* W_off  = (const float*)d_in[5];
    const float* b_off  = (const float*)d_in[6];
    const float* W_attn = (const float*)d_in[7];
    const float* b_attn = (const float*)d_in[8];
    const float* W_out  = (const float*)d_in[9];
    const float* b_out  = (const float*)d_in[10];

    float* out  = (float*)d_out;
    float* loc  = out + LOC_OFFSET;
    float* attn = out + ATTN_OFFSET;

    float* gv;
    float* gmid;
    float2* gmeta;
    cudaGetSymbolAddress((void**)&gv, g_v);
    cudaGetSymbolAddress((void**)&gmid, g_mid);
    cudaGetSymbolAddress((void**)&gmeta, g_meta);

    // 1. sampling offsets + fused location transform + gather meta
    {
        dim3 grid(1024 / 128, (BS * LQ) / TBM);      // 8 x 64
        gemm_fused<128, 1><<<grid, 256>>>(query, W_off, b_off, loc, refp, gmeta,
                                          BS * LQ, 1024, EMBED);
    }
    // 2. attn logits + fused softmax
    {
        dim3 grid(512 / 64, (BS * LQ) / TBM);        // 8 x 64
        gemm_fused<64, 2><<<grid, 256>>>(query, W_attn, b_attn, attn, nullptr, nullptr,
                                         BS * LQ, 512, EMBED);
    }
    // 3. value projection
    {
        dim3 grid(EMBED / 128, (BS * LEN_V) / TBM);  // 2 x 340
        gemm_fused<128, 0><<<grid, 256>>>(value, W_val, b_val, gv, nullptr, nullptr,
                                          BS * LEN_V, EMBED, EMBED);
    }
    // 4. slim bilinear gather
    gather_kernel<<<BS * LQ, 256>>>(gv, gmeta, attn, gmid);

    // 5. output projection
    {
        dim3 grid(EMBED / 128, (BS * LQ) / TBM);     // 2 x 64
        gemm_fused<128, 0><<<grid, 256>>>(gmid, W_out, b_out, out, nullptr, nullptr,
                                          BS * LQ, EMBED, EMBED);
    }
}

// round 8
// speedup vs baseline: 1.1752x; 1.1566x over previous
#include <cuda_runtime.h>
#include <cstdint>

// ---------------------------------------------------------------------------
// Problem constants
// ---------------------------------------------------------------------------
#define BS 4
#define LQ 1024
#define EMBED 256
#define NH 8
#define NL 4
#define NP 16
#define HD 32
#define LEN_V 5440

#define OUT_ELEMS   (BS * LQ * EMBED)
#define LOC_OFFSET  (OUT_ELEMS)
#define LOC_ELEMS   (BS * LQ * NH * NL * NP * 2)
#define ATTN_OFFSET (LOC_OFFSET + LOC_ELEMS)

__constant__ int   c_H[NL]      = {64, 32, 16, 8};
__constant__ int   c_W[NL]      = {64, 32, 16, 8};
__constant__ int   c_start[NL]  = {0, 4096, 5120, 5376};
__constant__ float c_invW[NL]   = {1.0f/64, 1.0f/32, 1.0f/16, 1.0f/8};
__constant__ float c_invH[NL]   = {1.0f/64, 1.0f/32, 1.0f/16, 1.0f/8};

__device__ float  g_v[BS * LEN_V * EMBED];            // projected value ~22.3 MB
__device__ float  g_mid[BS * LQ * EMBED];             // pre-W_out        4 MB
__device__ float2 g_meta[BS * LQ * NH * NL * NP * 4]; // gather meta     ~67 MB

// ---------------------------------------------------------------------------
// Packed f32x2 helpers
// ---------------------------------------------------------------------------
__device__ __forceinline__ uint64_t pack2(float x, float y) {
    uint64_t r;
    asm("mov.b64 %0, {%1, %2};" : "=l"(r) : "f"(x), "f"(y));
    return r;
}
__device__ __forceinline__ void unpack2(uint64_t v, float& x, float& y) {
    asm("mov.b64 {%0, %1}, %2;" : "=f"(x), "=f"(y) : "l"(v));
}
__device__ __forceinline__ void ffma2(uint64_t& d, uint64_t a, uint64_t b) {
    asm("fma.rn.f32x2 %0, %1, %2, %0;" : "+l"(d) : "l"(a), "l"(b));
}

// ---------------------------------------------------------------------------
// MEGA GEMM: three GEMMs (value-proj / offsets / attn-logits) in ONE launch.
// All share tile 64(M) x 128(N) x K=256, 256 threads, microtile 4x8.
//   CTAs [0,680):     value @ W_val  -> g_v            (mode 0)
//   CTAs [680,1192):  query @ W_off  -> loc + meta     (mode 1)
//   CTAs [1192,1448): query @ W_attn -> attn (softmax) (mode 2)
// ---------------------------------------------------------------------------
#define TBK 16
#define SA  68
#define SB  160           // 16 chunks * 10 floats
#define KK  256           // shared K for all three GEMMs

#define G3_CTAS 680
#define G1_CTAS 512
#define G2_CTAS 256
#define MEGA_CTAS (G3_CTAS + G1_CTAS + G2_CTAS)

__global__ __launch_bounds__(256) void mega_gemm(
    const float* __restrict__ query, const float* __restrict__ value,
    const float* __restrict__ W_val, const float* __restrict__ b_val,
    const float* __restrict__ W_off, const float* __restrict__ b_off,
    const float* __restrict__ W_attn, const float* __restrict__ b_attn,
    const float* __restrict__ refp,
    float* __restrict__ gv, float* __restrict__ loc,
    float* __restrict__ attn_out, float2* __restrict__ meta)
{
    __shared__ float As[2][TBK * SA];
    __shared__ float Bs[2][TBK * SB];

    const int cta = blockIdx.x;
    const float *A, *B, *bias;
    float* C;
    int N, mode, gx, gy;
    if (cta < G3_CTAS) {
        A = value; B = W_val; bias = b_val; C = gv;
        N = 256; mode = 0; gx = cta & 1; gy = cta >> 1;
    } else if (cta < G3_CTAS + G1_CTAS) {
        int l = cta - G3_CTAS;
        A = query; B = W_off; bias = b_off; C = loc;
        N = 1024; mode = 1; gx = l & 7; gy = l >> 3;
    } else {
        int l = cta - (G3_CTAS + G1_CTAS);
        A = query; B = W_attn; bias = b_attn; C = attn_out;
        N = 512; mode = 2; gx = l & 3; gy = l >> 2;
    }
    const int m0 = gy * 64;
    const int n0 = gx * 128;

    const int tid = threadIdx.x;
    const int tx  = tid & 15;
    const int ty  = tid >> 4;

    auto stage_a = [&](int buf, float4 v) {
        int m = tid >> 2, kq = tid & 3;
        float* p = &As[buf][(kq * 4) * SA + m];
        p[0 * SA] = v.x; p[1 * SA] = v.y; p[2 * SA] = v.z; p[3 * SA] = v.w;
    };
    auto stage_b = [&](int buf, float4 v, int i) {
        int kk = i >> 5;            // i / 32 float4-per-row
        int n4 = i & 31;
        float* p = &Bs[buf][kk * SB + (n4 >> 1) * 10 + (n4 & 1) * 4];
        *(float2*)(p)     = make_float2(v.x, v.y);
        *(float2*)(p + 2) = make_float2(v.z, v.w);
    };

    stage_a(0, *(const float4*)(A + (size_t)(m0 + (tid >> 2)) * KK + (tid & 3) * 4));
#pragma unroll
    for (int r = 0; r < 2; r++) {
        int i = tid + r * 256;
        stage_b(0, *(const float4*)(B + (size_t)(i >> 5) * N + n0 + (i & 31) * 4), i);
    }
    __syncthreads();

    uint64_t acc[4][4];
#pragma unroll
    for (int i = 0; i < 4; i++)
#pragma unroll
        for (int j = 0; j < 4; j++) acc[i][j] = 0ull;

    const int bofs = tx * 10;
    int cur = 0;

#pragma unroll 1
    for (int kt = 0; kt < KK / TBK; kt++) {
        float4 pa, pb[2];
        if (kt + 1 < KK / TBK) {
            const int k0 = (kt + 1) * TBK;
            pa = *(const float4*)(A + (size_t)(m0 + (tid >> 2)) * KK + k0 + (tid & 3) * 4);
#pragma unroll
            for (int r = 0; r < 2; r++) {
                int i = tid + r * 256;
                pb[r] = *(const float4*)(B + (size_t)(k0 + (i >> 5)) * N + n0 + (i & 31) * 4);
            }
        }

#pragma unroll
        for (int k = 0; k < TBK; k++) {
            float4 a4 = *(const float4*)&As[cur][k * SA + ty * 4];
            const uint64_t* bp = (const uint64_t*)&Bs[cur][k * SB + bofs];
            uint64_t bd[4];
#pragma unroll
            for (int j = 0; j < 4; j++) bd[j] = bp[j];
            uint64_t ad[4];
            ad[0] = pack2(a4.x, a4.x);
            ad[1] = pack2(a4.y, a4.y);
            ad[2] = pack2(a4.z, a4.z);
            ad[3] = pack2(a4.w, a4.w);
#pragma unroll
            for (int i = 0; i < 4; i++)
#pragma unroll
                for (int j = 0; j < 4; j++)
                    ffma2(acc[i][j], ad[i], bd[j]);
        }

        if (kt + 1 < KK / TBK) {
            const int nxt = cur ^ 1;
            stage_a(nxt, pa);
#pragma unroll
            for (int r = 0; r < 2; r++) stage_b(nxt, pb[r], tid + r * 256);
            __syncthreads();
            cur = nxt;
        }
    }

    float bn[8];
#pragma unroll
    for (int j = 0; j < 8; j++) bn[j] = __ldg(&bias[n0 + tx * 8 + j]);

    float o[4][8];
#pragma unroll
    for (int i = 0; i < 4; i++) {
#pragma unroll
        for (int j = 0; j < 4; j++)
            unpack2(acc[i][j], o[i][2 * j], o[i][2 * j + 1]);
#pragma unroll
        for (int j = 0; j < 8; j++) o[i][j] += bn[j];
    }

    if (mode == 0) {
        // ---- plain store (value projection) ----
#pragma unroll
        for (int i = 0; i < 4; i++) {
            float* crow = C + (size_t)(m0 + ty * 4 + i) * N + n0 + tx * 8;
            *(float4*)(crow)     = make_float4(o[i][0], o[i][1], o[i][2], o[i][3]);
            *(float4*)(crow + 4) = make_float4(o[i][4], o[i][5], o[i][6], o[i][7]);
        }
    } else if (mode == 1) {
        // ---- sampling-location transform + gather-meta precompute ----
        __syncthreads();
        float* rps = &As[0][0];
        if (tid < 128) {
            int row = tid >> 1, half = tid & 1;
            *(float4*)(rps + row * 8 + half * 4) =
                *(const float4*)(refp + (size_t)(m0 + row) * 8 + half * 4);
        }
        __syncthreads();

        const int h = gx;
        const int lvl = tx >> 2;
        const int W = c_W[lvl], H = c_H[lvl];
        const float fW = (float)W, fH = (float)H;
        const float invW = c_invW[lvl], invH = c_invH[lvl];
        const int cstE = c_start[lvl] * EMBED;

#pragma unroll
        for (int i = 0; i < 4; i++) {
            const int bq = m0 + ty * 4 + i;
            const float* rp = rps + (ty * 4 + i) * 8;
            float rx0 = rp[0], rx1 = rp[1], rx2 = rp[2], rx3 = rp[3];
            float ry0 = rp[4], ry1 = rp[5], ry2 = rp[6], ry3 = rp[7];
            float res[8];
#pragma unroll
            for (int j = 0; j < 8; j++) {
                int r = tx * 8 + j;
                int p = (r >> 1) & 15;
                int c = r & 1;
                float lam = (float)p * (1.0f / 15.0f);
                float pnt = c ? (((ry0 * lam + ry1) * lam + ry2) * lam + ry3)
                              : (((rx0 * lam + rx1) * lam + rx2) * lam + rx3);
                float inv = c ? invH : invW;
                res[j] = pnt + o[i][j] * inv;
            }
            float* crow = C + (size_t)bq * N + n0 + tx * 8;
            *(float4*)(crow)     = make_float4(res[0], res[1], res[2], res[3]);
            *(float4*)(crow + 4) = make_float4(res[4], res[5], res[6], res[7]);

            float2* mbase = meta + ((size_t)(bq * NH + h) * 64) * 4;
#pragma unroll
            for (int j = 0; j < 8; j += 2) {
                int p = ((tx * 8 + j) >> 1) & 15;
                int sp = lvl * NP + p;

                float x = res[j]     * fW - 0.5f;
                float y = res[j + 1] * fH - 0.5f;
                float x0f = floorf(x);
                float y0f = floorf(y);
                float wx = x - x0f;
                float wy = y - y0f;
                int x0 = (int)x0f, y0 = (int)y0f;
                int x1 = x0 + 1,   y1 = y0 + 1;

                bool vx0 = (x0 >= 0) & (x0 < W);
                bool vx1 = (x1 >= 0) & (x1 < W);
                bool vy0 = (y0 >= 0) & (y0 < H);
                bool vy1 = (y1 >= 0) & (y1 < H);

                float w00 = (vx0 & vy0) ? (1.0f - wx) * (1.0f - wy) : 0.0f;
                float w10 = (vx1 & vy0) ? wx * (1.0f - wy)          : 0.0f;
                float w01 = (vx0 & vy1) ? (1.0f - wx) * wy          : 0.0f;
                float w11 = (vx1 & vy1) ? wx * wy                   : 0.0f;

                int cx0 = min(max(x0, 0), W - 1);
                int cx1 = min(max(x1, 0), W - 1);
                int cy0 = min(max(y0, 0), H - 1);
                int cy1 = min(max(y1, 0), H - 1);

                int i00 = cstE + (cy0 * W + cx0) * EMBED;
                int i10 = cstE + (cy0 * W + cx1) * EMBED;
                int i01 = cstE + (cy1 * W + cx0) * EMBED;
                int i11 = cstE + (cy1 * W + cx1) * EMBED;

                float4* mp = (float4*)(mbase + sp * 4);
                mp[0] = make_float4(__int_as_float(i00), w00,
                                    __int_as_float(i10), w10);
                mp[1] = make_float4(__int_as_float(i01), w01,
                                    __int_as_float(i11), w11);
            }
        }
    } else {
        // ---- softmax over each 64-col head block (8 lanes x 8 vals) ----
#pragma unroll
        for (int i = 0; i < 4; i++) {
            float mx = o[i][0];
#pragma unroll
            for (int j = 1; j < 8; j++) mx = fmaxf(mx, o[i][j]);
#pragma unroll
            for (int off = 1; off < 8; off <<= 1)
                mx = fmaxf(mx, __shfl_xor_sync(0xFFFFFFFFu, mx, off));
            float e[8];
            float s = 0.0f;
#pragma unroll
            for (int j = 0; j < 8; j++) { e[j] = expf(o[i][j] - mx); s += e[j]; }
#pragma unroll
            for (int off = 1; off < 8; off <<= 1)
                s += __shfl_xor_sync(0xFFFFFFFFu, s, off);
            float inv = 1.0f / s;
            float* crow = C + (size_t)(m0 + ty * 4 + i) * N + n0 + tx * 8;
            *(float4*)(crow)     = make_float4(e[0]*inv, e[1]*inv, e[2]*inv, e[3]*inv);
            *(float4*)(crow + 4) = make_float4(e[4]*inv, e[5]*inv, e[6]*inv, e[7]*inv);
        }
    }
}

// ---------------------------------------------------------------------------
// Plain GEMM for the output projection (TN=128, mode-0 only).
// ---------------------------------------------------------------------------
__global__ __launch_bounds__(256) void gemm_out(
    const float* __restrict__ A, const float* __restrict__ B,
    const float* __restrict__ bias, float* __restrict__ C,
    int M, int N, int K)
{
    __shared__ float As[2][TBK * SA];
    __shared__ float Bs[2][TBK * SB];

    const int tid = threadIdx.x;
    const int tx  = tid & 15;
    const int ty  = tid >> 4;
    const int m0  = blockIdx.y * 64;
    const int n0  = blockIdx.x * 128;

    auto stage_a = [&](int buf, float4 v) {
        int m = tid >> 2, kq = tid & 3;
        float* p = &As[buf][(kq * 4) * SA + m];
        p[0 * SA] = v.x; p[1 * SA] = v.y; p[2 * SA] = v.z; p[3 * SA] = v.w;
    };
    auto stage_b = [&](int buf, float4 v, int i) {
        int kk = i >> 5;
        int n4 = i & 31;
        float* p = &Bs[buf][kk * SB + (n4 >> 1) * 10 + (n4 & 1) * 4];
        *(float2*)(p)     = make_float2(v.x, v.y);
        *(float2*)(p + 2) = make_float2(v.z, v.w);
    };

    stage_a(0, *(const float4*)(A + (size_t)(m0 + (tid >> 2)) * K + (tid & 3) * 4));
#pragma unroll
    for (int r = 0; r < 2; r++) {
        int i = tid + r * 256;
        stage_b(0, *(const float4*)(B + (size_t)(i >> 5) * N + n0 + (i & 31) * 4), i);
    }
    __syncthreads();

    uint64_t acc[4][4];
#pragma unroll
    for (int i = 0; i < 4; i++)
#pragma unroll
        for (int j = 0; j < 4; j++) acc[i][j] = 0ull;

    const int bofs = tx * 10;
    int cur = 0;

    for (int kt = 0; kt < K / TBK; kt++) {
        float4 pa, pb[2];
        if (kt + 1 < K / TBK) {
            const int k0 = (kt + 1) * TBK;
            pa = *(const float4*)(A + (size_t)(m0 + (tid >> 2)) * K + k0 + (tid & 3) * 4);
#pragma unroll
            for (int r = 0; r < 2; r++) {
                int i = tid + r * 256;
                pb[r] = *(const float4*)(B + (size_t)(k0 + (i >> 5)) * N + n0 + (i & 31) * 4);
            }
        }
#pragma unroll
        for (int k = 0; k < TBK; k++) {
            float4 a4 = *(const float4*)&As[cur][k * SA + ty * 4];
            const uint64_t* bp = (const uint64_t*)&Bs[cur][k * SB + bofs];
            uint64_t bd[4];
#pragma unroll
            for (int j = 0; j < 4; j++) bd[j] = bp[j];
            uint64_t ad[4];
            ad[0] = pack2(a4.x, a4.x);
            ad[1] = pack2(a4.y, a4.y);
            ad[2] = pack2(a4.z, a4.z);
            ad[3] = pack2(a4.w, a4.w);
#pragma unroll
            for (int i = 0; i < 4; i++)
#pragma unroll
                for (int j = 0; j < 4; j++)
                    ffma2(acc[i][j], ad[i], bd[j]);
        }
        if (kt + 1 < K / TBK) {
            const int nxt = cur ^ 1;
            stage_a(nxt, pa);
#pragma unroll
            for (int r = 0; r < 2; r++) stage_b(nxt, pb[r], tid + r * 256);
            __syncthreads();
            cur = nxt;
        }
    }

    float bn[8];
#pragma unroll
    for (int j = 0; j < 8; j++) bn[j] = __ldg(&bias[n0 + tx * 8 + j]);
#pragma unroll
    for (int i = 0; i < 4; i++) {
        float o[8];
#pragma unroll
        for (int j = 0; j < 4; j++)
            unpack2(acc[i][j], o[2 * j], o[2 * j + 1]);
#pragma unroll
        for (int j = 0; j < 8; j++) o[j] += bn[j];
        float* crow = C + (size_t)(m0 + ty * 4 + i) * N + n0 + tx * 8;
        *(float4*)(crow)     = make_float4(o[0], o[1], o[2], o[3]);
        *(float4*)(crow + 4) = make_float4(o[4], o[5], o[6], o[7]);
    }
}

// ---------------------------------------------------------------------------
// Branchless gather: warp per (b,q,h); lane = (corner, channel-group).
// No control dependency on the loads -> ptxas can batch them (high MLP).
// ---------------------------------------------------------------------------
__global__ __launch_bounds__(256) void gather_kernel(
    const float* __restrict__ v,
    const float2* __restrict__ meta,
    const float* __restrict__ attn,
    float* __restrict__ out)
{
    const int bq = blockIdx.x;
    const int b = bq >> 10;
    const int h = threadIdx.x >> 5;
    const int lane = threadIdx.x & 31;
    const int corner = lane >> 3;
    const int cg = lane & 7;

    const float2* mh = meta + ((size_t)(bq * NH + h) * 64) * 4 + corner;
    const float*  ah = attn + ((size_t)bq * NH + h) * 64;
    const float*  vb = v + (size_t)b * LEN_V * EMBED + h * HD + cg * 4;

    float4 acc = make_float4(0.f, 0.f, 0.f, 0.f);

#pragma unroll 8
    for (int sp = 0; sp < 64; sp++) {
        float2 mw = __ldg(&mh[sp * 4]);
        float a = __ldg(&ah[sp]);
        int idx = __float_as_int(mw.x);           // always a valid clamped index
        float4 vv = *(const float4*)(vb + idx);   // unconditional load
        float w = mw.y * a;                        // 0 when corner invalid
        acc.x = fmaf(w, vv.x, acc.x);
        acc.y = fmaf(w, vv.y, acc.y);
        acc.z = fmaf(w, vv.z, acc.z);
        acc.w = fmaf(w, vv.w, acc.w);
    }

#pragma unroll
    for (int off = 8; off <= 16; off <<= 1) {
        acc.x += __shfl_xor_sync(0xFFFFFFFFu, acc.x, off);
        acc.y += __shfl_xor_sync(0xFFFFFFFFu, acc.y, off);
        acc.z += __shfl_xor_sync(0xFFFFFFFFu, acc.z, off);
        acc.w += __shfl_xor_sync(0xFFFFFFFFu, acc.w, off);
    }

    if (lane < 8) {
        float* orow = out + ((size_t)bq * NH + h) * HD + cg * 4;
        *(float4*)orow = acc;
    }
}

// ---------------------------------------------------------------------------
// Launch
// ---------------------------------------------------------------------------
extern "C" void kernel_launch(void* const* d_in, const int* in_sizes, int n_in,
                              void* d_out, int out_size)
{
    const float* query  = (const float*)d_in[0];
    const float* refp   = (const float*)d_in[1];
    const float* value  = (const float*)d_in[2];
    const float* W_val  = (const float*)d_in[3];
    const float* b_val  = (const float*)d_in[4];
    const float* W_off  = (const float*)d_in[5];
    const float* b_off  = (const float*)d_in[6];
    const float* W_attn = (const float*)d_in[7];
    const float* b_attn = (const float*)d_in[8];
    const float* W_out  = (const float*)d_in[9];
    const float* b_out  = (const float*)d_in[10];

    float* out  = (float*)d_out;
    float* loc  = out + LOC_OFFSET;
    float* attn = out + ATTN_OFFSET;

    float* gv;
    float* gmid;
    float2* gmeta;
    cudaGetSymbolAddress((void**)&gv, g_v);
    cudaGetSymbolAddress((void**)&gmid, g_mid);
    cudaGetSymbolAddress((void**)&gmeta, g_meta);

    // 1. all three front GEMMs in one launch (1448 CTAs)
    mega_gemm<<<MEGA_CTAS, 256>>>(query, value, W_val, b_val, W_off, b_off,
                                  W_attn, b_attn, refp, gv, loc, attn, gmeta);

    // 2. branchless bilinear gather
    gather_kernel<<<BS * LQ, 256>>>(gv, gmeta, attn, gmid);

    // 3. output projection
    {
        dim3 grid(EMBED / 128, (BS * LQ) / 64);
        gemm_out<<<grid, 256>>>(gmid, W_out, b_out, out, BS * LQ, EMBED, EMBED);
    }
}

// round 10
// speedup vs baseline: 1.2611x; 1.0731x over previous
#include <cuda_runtime.h>
#include <cstdint>

// ---------------------------------------------------------------------------
// Problem constants
// ---------------------------------------------------------------------------
#define BS 4
#define LQ 1024
#define EMBED 256
#define NH 8
#define NL 4
#define NP 16
#define HD 32
#define LEN_V 5440

#define OUT_ELEMS   (BS * LQ * EMBED)
#define LOC_OFFSET  (OUT_ELEMS)
#define LOC_ELEMS   (BS * LQ * NH * NL * NP * 2)
#define ATTN_OFFSET (LOC_OFFSET + LOC_ELEMS)

__constant__ int   c_H[NL]      = {64, 32, 16, 8};
__constant__ int   c_W[NL]      = {64, 32, 16, 8};
__constant__ int   c_start[NL]  = {0, 4096, 5120, 5376};
__constant__ float c_invW[NL]   = {1.0f/64, 1.0f/32, 1.0f/16, 1.0f/8};
__constant__ float c_invH[NL]   = {1.0f/64, 1.0f/32, 1.0f/16, 1.0f/8};

__device__ float  g_v[BS * LEN_V * EMBED];            // projected value ~22.3 MB
__device__ float  g_mid[BS * LQ * EMBED];             // pre-W_out        4 MB
__device__ float2 g_meta[BS * LQ * NH * NL * NP * 4]; // gather meta     ~67 MB

// ---------------------------------------------------------------------------
// Packed f32x2 helpers
// ---------------------------------------------------------------------------
__device__ __forceinline__ uint64_t pack2(float x, float y) {
    uint64_t r;
    asm("mov.b64 %0, {%1, %2};" : "=l"(r) : "f"(x), "f"(y));
    return r;
}
__device__ __forceinline__ void unpack2(uint64_t v, float& x, float& y) {
    asm("mov.b64 {%0, %1}, %2;" : "=f"(x), "=f"(y) : "l"(v));
}
__device__ __forceinline__ void ffma2(uint64_t& d, uint64_t a, uint64_t b) {
    asm("fma.rn.f32x2 %0, %1, %2, %0;" : "+l"(d) : "l"(a), "l"(b));
}

// ---------------------------------------------------------------------------
// Tiling: 64(M) x 128(N) x BK=16, 256 threads.
// Warp grid 2(m) x 4(n); warp tile 32m x 32n.
// Lane: lm = lane&7 (m group), ln = lane>>3 (n group).
//   A read : float4 at m = wm*32+lm*4       -> 8 distinct/warp, 4-lane bcast
//   B read : 4 x LDS.64, chunk = wn*4+ln    -> 4 distinct/warp, 8-lane bcast
//            chunk stride 10 floats (40 B, 8B-aligned) -> banks
//            {0,10,20,30}+2j across the 4 groups: conflict-free
// ---------------------------------------------------------------------------
#define TBK 16
#define SA  68
#define SB  160           // 16 chunks * 10 floats
#define KK  256

#define SMSTRIDE 132      // softmax stage row stride (mod 4 == 0: float4-safe)
#define SMEM_BYTES 33792  // max(gemm bufs 29184, softmax stage 64*132*4=33792)

#define G3_CTAS 680
#define G1_CTAS 512
#define G2_CTAS 256
#define MEGA_CTAS (G3_CTAS + G1_CTAS + G2_CTAS)

// Shared mainloop: computes the 64x128 tile accumulation into acc.
template <typename LdA, typename LdB>
__device__ __forceinline__ void gemm_mainloop(
    float* As, float* Bs,   // [2][TBK*SA], [2][TBK*SB] flat
    LdA ldA, LdB ldB, int KT,
    int tid, int wm, int lm, int wn, int ln,
    uint64_t (&acc)[4][4])
{
    auto stage_a = [&](int buf, float4 v) {
        int m = tid >> 2, kq = tid & 3;
        float* p = As + buf * (TBK * SA) + (kq * 4) * SA + m;
        p[0 * SA] = v.x; p[1 * SA] = v.y; p[2 * SA] = v.z; p[3 * SA] = v.w;
    };
    auto stage_b = [&](int buf, float4 v, int i) {
        int kk = i >> 5;
        int n4 = i & 31;
        float* p = Bs + buf * (TBK * SB) + kk * SB + (n4 >> 1) * 10 + (n4 & 1) * 4;
        *(float2*)(p)     = make_float2(v.x, v.y);
        *(float2*)(p + 2) = make_float2(v.z, v.w);
    };

    stage_a(0, ldA(0));
    stage_b(0, ldB(0, tid), tid);
    stage_b(0, ldB(0, tid + 256), tid + 256);
    __syncthreads();

    const int aofs = wm * 32 + lm * 4;
    const int bofs = (wn * 4 + ln) * 10;
    int cur = 0;

#pragma unroll 1
    for (int kt = 0; kt < KT; kt++) {
        float4 pa, pb0, pb1;
        if (kt + 1 < KT) {
            pa  = ldA(kt + 1);
            pb0 = ldB(kt + 1, tid);
            pb1 = ldB(kt + 1, tid + 256);
        }

#pragma unroll
        for (int k = 0; k < TBK; k++) {
            float4 a4 = *(const float4*)(As + cur * (TBK * SA) + k * SA + aofs);
            const uint64_t* bp = (const uint64_t*)(Bs + cur * (TBK * SB) + k * SB + bofs);
            uint64_t bd[4];
            bd[0] = bp[0]; bd[1] = bp[1]; bd[2] = bp[2]; bd[3] = bp[3];
            uint64_t ad[4];
            ad[0] = pack2(a4.x, a4.x);
            ad[1] = pack2(a4.y, a4.y);
            ad[2] = pack2(a4.z, a4.z);
            ad[3] = pack2(a4.w, a4.w);
#pragma unroll
            for (int i = 0; i < 4; i++)
#pragma unroll
                for (int j = 0; j < 4; j++)
                    ffma2(acc[i][j], ad[i], bd[j]);
        }

        if (kt + 1 < KT) {
            const int nxt = cur ^ 1;
            stage_a(nxt, pa);
            stage_b(nxt, pb0, tid);
            stage_b(nxt, pb1, tid + 256);
            __syncthreads();
            cur = nxt;
        }
    }
}

// ---------------------------------------------------------------------------
// MEGA GEMM: three front GEMMs in one launch.
// ---------------------------------------------------------------------------
__global__ __launch_bounds__(256, 3) void mega_gemm(
    const float* __restrict__ query, const float* __restrict__ value,
    const float* __restrict__ W_val, const float* __restrict__ b_val,
    const float* __restrict__ W_off, const float* __restrict__ b_off,
    const float* __restrict__ W_attn, const float* __restrict__ b_attn,
    const float* __restrict__ refp,
    float* __restrict__ gv, float* __restrict__ loc,
    float* __restrict__ attn_out, float2* __restrict__ meta)
{
    __shared__ __align__(16) char smem_raw[SMEM_BYTES];
    float* As = (float*)smem_raw;
    float* Bs = As + 2 * (TBK * SA);

    const int cta = blockIdx.x;
    const float *A, *B, *bias;
    float* C;
    int N, mode, gx, gy;
    if (cta < G3_CTAS) {
        A = value; B = W_val; bias = b_val; C = gv;
        N = 256; mode = 0; gx = cta & 1; gy = cta >> 1;
    } else if (cta < G3_CTAS + G1_CTAS) {
        int l = cta - G3_CTAS;
        A = query; B = W_off; bias = b_off; C = loc;
        N = 1024; mode = 1; gx = l & 7; gy = l >> 3;
    } else {
        int l = cta - (G3_CTAS + G1_CTAS);
        A = query; B = W_attn; bias = b_attn; C = attn_out;
        N = 512; mode = 2; gx = l & 3; gy = l >> 2;
    }
    const int m0 = gy * 64;
    const int n0 = gx * 128;

    const int tid  = threadIdx.x;
    const int lane = tid & 31;
    const int wid  = tid >> 5;
    const int wm   = wid >> 2;
    const int wn   = wid & 3;
    const int lm   = lane & 7;
    const int ln   = lane >> 3;

    uint64_t acc[4][4];
#pragma unroll
    for (int i = 0; i < 4; i++)
#pragma unroll
        for (int j = 0; j < 4; j++) acc[i][j] = 0ull;

    auto ldA = [&](int kt) {
        return *(const float4*)(A + (size_t)(m0 + (tid >> 2)) * KK + kt * TBK + (tid & 3) * 4);
    };
    auto ldB = [&](int kt, int i) {
        return *(const float4*)(B + (size_t)(kt * TBK + (i >> 5)) * N + n0 + (i & 31) * 4);
    };
    gemm_mainloop(As, Bs, ldA, ldB, KK / TBK, tid, wm, lm, wn, ln, acc);

    const int nb = wn * 32 + ln * 8;          // n offset within tile
    const int mb = wm * 32 + lm * 4;          // m offset within tile

    float bn[8];
#pragma unroll
    for (int j = 0; j < 8; j++) bn[j] = __ldg(&bias[n0 + nb + j]);

    float o[4][8];
#pragma unroll
    for (int i = 0; i < 4; i++) {
#pragma unroll
        for (int j = 0; j < 4; j++)
            unpack2(acc[i][j], o[i][2 * j], o[i][2 * j + 1]);
#pragma unroll
        for (int j = 0; j < 8; j++) o[i][j] += bn[j];
    }

    if (mode == 0) {
#pragma unroll
        for (int i = 0; i < 4; i++) {
            float* crow = C + (size_t)(m0 + mb + i) * N + n0 + nb;
            *(float4*)(crow)     = make_float4(o[i][0], o[i][1], o[i][2], o[i][3]);
            *(float4*)(crow + 4) = make_float4(o[i][4], o[i][5], o[i][6], o[i][7]);
        }
    } else if (mode == 1) {
        // ---- sampling-location transform + gather-meta precompute ----
        __syncthreads();
        float* rps = As;                       // 64 x 8 floats
        if (tid < 128) {
            int row = tid >> 1, half = tid & 1;
            *(float4*)(rps + row * 8 + half * 4) =
                *(const float4*)(refp + (size_t)(m0 + row) * 8 + half * 4);
        }
        __syncthreads();

        const int h = gx;
        const int lvl = wn;                    // warp-uniform level
        const int W = c_W[lvl], H = c_H[lvl];
        const float fW = (float)W, fH = (float)H;
        const float invW = c_invW[lvl], invH = c_invH[lvl];
        const int cstE = c_start[lvl] * EMBED;

#pragma unroll
        for (int i = 0; i < 4; i++) {
            const int bq = m0 + mb + i;
            const float* rp = rps + (mb + i) * 8;
            float rx0 = rp[0], rx1 = rp[1], rx2 = rp[2], rx3 = rp[3];
            float ry0 = rp[4], ry1 = rp[5], ry2 = rp[6], ry3 = rp[7];
            float res[8];
#pragma unroll
            for (int j = 0; j < 8; j++) {
                int rr = ln * 8 + j;           // 0..31 within level block
                int p = rr >> 1;
                int c = j & 1;
                float lam = (float)p * (1.0f / 15.0f);
                float pnt = c ? (((ry0 * lam + ry1) * lam + ry2) * lam + ry3)
                              : (((rx0 * lam + rx1) * lam + rx2) * lam + rx3);
                float inv = c ? invH : invW;
                res[j] = pnt + o[i][j] * inv;
            }
            float* crow = C + (size_t)bq * N + n0 + nb;
            *(float4*)(crow)     = make_float4(res[0], res[1], res[2], res[3]);
            *(float4*)(crow + 4) = make_float4(res[4], res[5], res[6], res[7]);

            float2* mbase = meta + ((size_t)(bq * NH + h) * 64) * 4;
#pragma unroll
            for (int j = 0; j < 8; j += 2) {
                int p = (ln * 8 + j) >> 1;
                int sp = lvl * NP + p;

                float x = res[j]     * fW - 0.5f;
                float y = res[j + 1] * fH - 0.5f;
                float x0f = floorf(x);
                float y0f = floorf(y);
                float wx = x - x0f;
                float wy = y - y0f;
                int x0 = (int)x0f, y0 = (int)y0f;
                int x1 = x0 + 1,   y1 = y0 + 1;

                bool vx0 = (x0 >= 0) & (x0 < W);
                bool vx1 = (x1 >= 0) & (x1 < W);
                bool vy0 = (y0 >= 0) & (y0 < H);
                bool vy1 = (y1 >= 0) & (y1 < H);

                float w00 = (vx0 & vy0) ? (1.0f - wx) * (1.0f - wy) : 0.0f;
                float w10 = (vx1 & vy0) ? wx * (1.0f - wy)          : 0.0f;
                float w01 = (vx0 & vy1) ? (1.0f - wx) * wy          : 0.0f;
                float w11 = (vx1 & vy1) ? wx * wy                   : 0.0f;

                int cx0 = min(max(x0, 0), W - 1);
                int cx1 = min(max(x1, 0), W - 1);
                int cy0 = min(max(y0, 0), H - 1);
                int cy1 = min(max(y1, 0), H - 1);

                int i00 = cstE + (cy0 * W + cx0) * EMBED;
                int i10 = cstE + (cy0 * W + cx1) * EMBED;
                int i01 = cstE + (cy1 * W + cx0) * EMBED;
                int i11 = cstE + (cy1 * W + cx1) * EMBED;

                float4* mp = (float4*)(mbase + sp * 4);
                mp[0] = make_float4(__int_as_float(i00), w00,
                                    __int_as_float(i10), w10);
                mp[1] = make_float4(__int_as_float(i01), w01,
                                    __int_as_float(i11), w11);
            }
        }
    } else {
        // ---- softmax: stage tile to smem, row-wise reduce (2 heads/tile) ----
        __syncthreads();
        float* stage = (float*)smem_raw;       // 64 rows x SMSTRIDE floats
#pragma unroll
        for (int i = 0; i < 4; i++) {
            float* srow = stage + (mb + i) * SMSTRIDE + nb;
            *(float4*)(srow)     = make_float4(o[i][0], o[i][1], o[i][2], o[i][3]);
            *(float4*)(srow + 4) = make_float4(o[i][4], o[i][5], o[i][6], o[i][7]);
        }
        __syncthreads();

        // 256 threads -> 128 row-heads x 2 halves of 32 cols
        const int rh   = tid >> 1;
        const int half = tid & 1;
        const int row  = rh >> 1;
        const int head = rh & 1;
        const float* srow = stage + row * SMSTRIDE + head * 64 + half * 32;

        float v[32];
#pragma unroll
        for (int q = 0; q < 8; q++)
            *(float4*)(v + q * 4) = *(const float4*)(srow + q * 4);

        float mx = v[0];
#pragma unroll
        for (int q = 1; q < 32; q++) mx = fmaxf(mx, v[q]);
        mx = fmaxf(mx, __shfl_xor_sync(0xFFFFFFFFu, mx, 1));

        float s = 0.0f;
#pragma unroll
        for (int q = 0; q < 32; q++) { v[q] = expf(v[q] - mx); s += v[q]; }
        s += __shfl_xor_sync(0xFFFFFFFFu, s, 1);
        float inv = 1.0f / s;

        float* crow = C + (size_t)(m0 + row) * N + n0 + head * 64 + half * 32;
#pragma unroll
        for (int q = 0; q < 8; q++) {
            float4 w = make_float4(v[q*4+0]*inv, v[q*4+1]*inv,
                                   v[q*4+2]*inv, v[q*4+3]*inv);
            *(float4*)(crow + q * 4) = w;
        }
    }
}

// ---------------------------------------------------------------------------
// Output projection GEMM (mode-0 only, same broadcast mapping).
// ---------------------------------------------------------------------------
__global__ __launch_bounds__(256, 3) void gemm_out(
    const float* __restrict__ A, const float* __restrict__ B,
    const float* __restrict__ bias, float* __restrict__ C,
    int M, int N, int K)
{
    __shared__ __align__(16) char smem_raw[SMEM_BYTES];
    float* As = (float*)smem_raw;
    float* Bs = As + 2 * (TBK * SA);

    const int tid  = threadIdx.x;
    const int lane = tid & 31;
    const int wid  = tid >> 5;
    const int wm   = wid >> 2;
    const int wn   = wid & 3;
    const int lm   = lane & 7;
    const int ln   = lane >> 3;
    const int m0   = blockIdx.y * 64;
    const int n0   = blockIdx.x * 128;

    uint64_t acc[4][4];
#pragma unroll
    for (int i = 0; i < 4; i++)
#pragma unroll
        for (int j = 0; j < 4; j++) acc[i][j] = 0ull;

    auto ldA = [&](int kt) {
        return *(const float4*)(A + (size_t)(m0 + (tid >> 2)) * K + kt * TBK + (tid & 3) * 4);
    };
    auto ldB = [&](int kt, int i) {
        return *(const float4*)(B + (size_t)(kt * TBK + (i >> 5)) * N + n0 + (i & 31) * 4);
    };
    gemm_mainloop(As, Bs, ldA, ldB, K / TBK, tid, wm, lm, wn, ln, acc);

    const int nb = wn * 32 + ln * 8;
    const int mb = wm * 32 + lm * 4;

    float bn[8];
#pragma unroll
    for (int j = 0; j < 8; j++) bn[j] = __ldg(&bias[n0 + nb + j]);

#pragma unroll
    for (int i = 0; i < 4; i++) {
        float o[8];
#pragma unroll
        for (int j = 0; j < 4; j++)
            unpack2(acc[i][j], o[2 * j], o[2 * j + 1]);
#pragma unroll
        for (int j = 0; j < 8; j++) o[j] += bn[j];
        float* crow = C + (size_t)(m0 + mb + i) * N + n0 + nb;
        *(float4*)(crow)     = make_float4(o[0], o[1], o[2], o[3]);
        *(float4*)(crow + 4) = make_float4(o[4], o[5], o[6], o[7]);
    }
}

// ---------------------------------------------------------------------------
// Branchless gather: warp per (b,q,h); lane = (corner, channel-group).
// ---------------------------------------------------------------------------
__global__ __launch_bounds__(256) void gather_kernel(
    const float* __restrict__ v,
    const float2* __restrict__ meta,
    const float* __restrict__ attn,
    float* __restrict__ out)
{
    const int bq = blockIdx.x;
    const int b = bq >> 10;
    const int h = threadIdx.x >> 5;
    const int lane = threadIdx.x & 31;
    const int corner = lane >> 3;
    const int cg = lane & 7;

    const float2* mh = meta + ((size_t)(bq * NH + h) * 64) * 4 + corner;
    const float*  ah = attn + ((size_t)bq * NH + h) * 64;
    const float*  vb = v + (size_t)b * LEN_V * EMBED + h * HD + cg * 4;

    float4 acc = make_float4(0.f, 0.f, 0.f, 0.f);

#pragma unroll 8
    for (int sp = 0; sp < 64; sp++) {
        float2 mw = __ldg(&mh[sp * 4]);
        float a = __ldg(&ah[sp]);
        int idx = __float_as_int(mw.x);
        float4 vv = *(const float4*)(vb + idx);
        float w = mw.y * a;
        acc.x = fmaf(w, vv.x, acc.x);
        acc.y = fmaf(w, vv.y, acc.y);
        acc.z = fmaf(w, vv.z, acc.z);
        acc.w = fmaf(w, vv.w, acc.w);
    }

#pragma unroll
    for (int off = 8; off <= 16; off <<= 1) {
        acc.x += __shfl_xor_sync(0xFFFFFFFFu, acc.x, off);
        acc.y += __shfl_xor_sync(0xFFFFFFFFu, acc.y, off);
        acc.z += __shfl_xor_sync(0xFFFFFFFFu, acc.z, off);
        acc.w += __shfl_xor_sync(0xFFFFFFFFu, acc.w, off);
    }

    if (lane < 8) {
        float* orow = out + ((size_t)bq * NH + h) * HD + cg * 4;
        *(float4*)orow = acc;
    }
}

// ---------------------------------------------------------------------------
// Launch
// ---------------------------------------------------------------------------
extern "C" void kernel_launch(void* const* d_in, const int* in_sizes, int n_in,
                              void* d_out, int out_size)
{
    const float* query  = (const float*)d_in[0];
    const float* refp   = (const float*)d_in[1];
    const float* value  = (const float*)d_in[2];
    const float* W_val  = (const float*)d_in[3];
    const float* b_val  = (const float*)d_in[4];
    const float* W_off  = (const float*)d_in[5];
    const float* b_off  = (const float*)d_in[6];
    const float* W_attn = (const float*)d_in[7];
    const float* b_attn = (const float*)d_in[8];
    const float* W_out  = (const float*)d_in[9];
    const float* b_out  = (const float*)d_in[10];

    float* out  = (float*)d_out;
    float* loc  = out + LOC_OFFSET;
    float* attn = out + ATTN_OFFSET;

    float* gv;
    float* gmid;
    float2* gmeta;
    cudaGetSymbolAddress((void**)&gv, g_v);
    cudaGetSymbolAddress((void**)&gmid, g_mid);
    cudaGetSymbolAddress((void**)&gmeta, g_meta);

    // 1. all three front GEMMs in one launch
    mega_gemm<<<MEGA_CTAS, 256>>>(query, value, W_val, b_val, W_off, b_off,
                                  W_attn, b_attn, refp, gv, loc, attn, gmeta);

    // 2. branchless bilinear gather
    gather_kernel<<<BS * LQ, 256>>>(gv, gmeta, attn, gmid);

    // 3. output projection
    {
        dim3 grid(EMBED / 128, (BS * LQ) / 64);
        gemm_out<<<grid, 256>>>(gmid, W_out, b_out, out, BS * LQ, EMBED, EMBED);
    }
}

// round 11
// speedup vs baseline: 1.2660x; 1.0039x over previous
#include <cuda_runtime.h>
#include <cstdint>

// ---------------------------------------------------------------------------
// Problem constants
// ---------------------------------------------------------------------------
#define BS 4
#define LQ 1024
#define EMBED 256
#define NH 8
#define NL 4
#define NP 16
#define HD 32
#define LEN_V 5440

#define OUT_ELEMS   (BS * LQ * EMBED)
#define LOC_OFFSET  (OUT_ELEMS)
#define LOC_ELEMS   (BS * LQ * NH * NL * NP * 2)
#define ATTN_OFFSET (LOC_OFFSET + LOC_ELEMS)

__constant__ int   c_H[NL]      = {64, 32, 16, 8};
__constant__ int   c_W[NL]      = {64, 32, 16, 8};
__constant__ int   c_start[NL]  = {0, 4096, 5120, 5376};
__constant__ float c_invW[NL]   = {1.0f/64, 1.0f/32, 1.0f/16, 1.0f/8};
__constant__ float c_invH[NL]   = {1.0f/64, 1.0f/32, 1.0f/16, 1.0f/8};

__device__ float  g_v[BS * LEN_V * EMBED];            // projected value ~22.3 MB
__device__ float  g_mid[BS * LQ * EMBED];             // pre-W_out        4 MB
__device__ float2 g_meta[BS * LQ * NH * NL * NP * 4]; // gather meta     ~67 MB

// ---------------------------------------------------------------------------
// Packed f32x2 helpers
// ---------------------------------------------------------------------------
__device__ __forceinline__ uint64_t pack2(float x, float y) {
    uint64_t r;
    asm("mov.b64 %0, {%1, %2};" : "=l"(r) : "f"(x), "f"(y));
    return r;
}
__device__ __forceinline__ void unpack2(uint64_t v, float& x, float& y) {
    asm("mov.b64 {%0, %1}, %2;" : "=f"(x), "=f"(y) : "l"(v));
}
__device__ __forceinline__ void ffma2(uint64_t& d, uint64_t a, uint64_t b) {
    asm("fma.rn.f32x2 %0, %1, %2, %0;" : "+l"(d) : "l"(a), "l"(b));
}

// ---------------------------------------------------------------------------
// Tiling: 128(M) x 128(N) x BK=16, 256 threads, microtile 8m x 8n.
// Warp grid 4(m) x 2(n); warp tile 32m x 64n.
// Lane: lm = lane&3 (m group of 8 rows), ln = lane>>2 (n group of 8 cols).
//   A read : 2x LDS.128 at m = wm*32+lm*8     (4 distinct, 8-lane bcast)
//   B read : 2x LDS.128 at chunk = wn*8+ln    (8 distinct, 4-lane bcast)
//            chunk stride 12 floats (48B, 16B-aligned) -> the 8 chunks hit
//            banks {0,12,24,4,16,28,8,20}: each load covers all 32 banks
//            exactly once -> conflict-free.
// Per warp-k: 4 LDS.128 for 64 FFMA2.
// ---------------------------------------------------------------------------
#define TBM 128
#define TBK 16
#define SA  132           // A row stride (m + pad)
#define SB  192           // 16 chunks * 12 floats
#define KK  256

#define SMEM_BYTES ((2 * TBK * SA + 2 * TBK * SB) * 4)   // 16896 + 24576 = 41472

#define G3_CTAS 340       // value proj : 170(gy) x 2(gx)
#define G1_CTAS 256       // offsets    : 32(gy) x 8(gx)
#define G2_CTAS 128       // attn       : 32(gy) x 4(gx)
#define MEGA_CTAS (G3_CTAS + G1_CTAS + G2_CTAS)

// Shared mainloop: 128x128 tile accumulation into acc[8][4] (f32x2 pairs).
template <typename LdA, typename LdB>
__device__ __forceinline__ void gemm_mainloop(
    float* As, float* Bs, LdA ldA, LdB ldB, int KT,
    int tid, int aofs, int bofs, uint64_t (&acc)[8][4])
{
    auto stage_a = [&](int buf, float4 v, int i) {
        int row = i >> 2, kq = i & 3;
        float* p = As + buf * (TBK * SA) + (kq * 4) * SA + row;
        p[0 * SA] = v.x; p[1 * SA] = v.y; p[2 * SA] = v.z; p[3 * SA] = v.w;
    };
    auto stage_b = [&](int buf, float4 v, int i) {
        int kk = i >> 5, n4 = i & 31;
        *(float4*)(Bs + buf * (TBK * SB) + kk * SB + (n4 >> 1) * 12 + (n4 & 1) * 4) = v;
    };

    stage_a(0, ldA(0, tid), tid);
    stage_a(0, ldA(0, tid + 256), tid + 256);
    stage_b(0, ldB(0, tid), tid);
    stage_b(0, ldB(0, tid + 256), tid + 256);
    __syncthreads();

    int cur = 0;

#pragma unroll 1
    for (int kt = 0; kt < KT; kt++) {
        float4 pa0, pa1, pb0, pb1;
        if (kt + 1 < KT) {
            pa0 = ldA(kt + 1, tid);
            pa1 = ldA(kt + 1, tid + 256);
            pb0 = ldB(kt + 1, tid);
            pb1 = ldB(kt + 1, tid + 256);
        }

#pragma unroll
        for (int k = 0; k < TBK; k++) {
            const float* ap = As + cur * (TBK * SA) + k * SA + aofs;
            float4 a0 = *(const float4*)(ap);
            float4 a1 = *(const float4*)(ap + 4);
            const uint64_t* bp = (const uint64_t*)(Bs + cur * (TBK * SB) + k * SB + bofs);
            uint64_t bd[4];
            bd[0] = bp[0]; bd[1] = bp[1]; bd[2] = bp[2]; bd[3] = bp[3];
            uint64_t ad[8];
            ad[0] = pack2(a0.x, a0.x);
            ad[1] = pack2(a0.y, a0.y);
            ad[2] = pack2(a0.z, a0.z);
            ad[3] = pack2(a0.w, a0.w);
            ad[4] = pack2(a1.x, a1.x);
            ad[5] = pack2(a1.y, a1.y);
            ad[6] = pack2(a1.z, a1.z);
            ad[7] = pack2(a1.w, a1.w);
#pragma unroll
            for (int i = 0; i < 8; i++)
#pragma unroll
                for (int j = 0; j < 4; j++)
                    ffma2(acc[i][j], ad[i], bd[j]);
        }

        if (kt + 1 < KT) {
            const int nxt = cur ^ 1;
            stage_a(nxt, pa0, tid);
            stage_a(nxt, pa1, tid + 256);
            stage_b(nxt, pb0, tid);
            stage_b(nxt, pb1, tid + 256);
            __syncthreads();
            cur = nxt;
        }
    }
}

// ---------------------------------------------------------------------------
// MEGA GEMM: three front GEMMs in one launch.
// ---------------------------------------------------------------------------
__global__ __launch_bounds__(256, 2) void mega_gemm(
    const float* __restrict__ query, const float* __restrict__ value,
    const float* __restrict__ W_val, const float* __restrict__ b_val,
    const float* __restrict__ W_off, const float* __restrict__ b_off,
    const float* __restrict__ W_attn, const float* __restrict__ b_attn,
    const float* __restrict__ refp,
    float* __restrict__ gv, float* __restrict__ loc,
    float* __restrict__ attn_out, float2* __restrict__ meta)
{
    __shared__ __align__(16) char smem_raw[SMEM_BYTES];
    float* As = (float*)smem_raw;
    float* Bs = As + 2 * (TBK * SA);

    const int cta = blockIdx.x;
    const float *A, *B, *bias;
    float* C;
    int N, mode, gx, gy;
    if (cta < G3_CTAS) {
        A = value; B = W_val; bias = b_val; C = gv;
        N = 256; mode = 0; gx = cta & 1; gy = cta >> 1;
    } else if (cta < G3_CTAS + G1_CTAS) {
        int l = cta - G3_CTAS;
        A = query; B = W_off; bias = b_off; C = loc;
        N = 1024; mode = 1; gx = l & 7; gy = l >> 3;
    } else {
        int l = cta - (G3_CTAS + G1_CTAS);
        A = query; B = W_attn; bias = b_attn; C = attn_out;
        N = 512; mode = 2; gx = l & 3; gy = l >> 2;
    }
    const int m0 = gy * TBM;
    const int n0 = gx * 128;

    const int tid  = threadIdx.x;
    const int lane = tid & 31;
    const int wid  = tid >> 5;
    const int wm   = wid & 3;
    const int wn   = wid >> 2;
    const int lm   = lane & 3;
    const int ln   = lane >> 2;

    const int aofs = wm * 32 + lm * 8;
    const int bofs = (wn * 8 + ln) * 12;
    const int mb   = wm * 32 + lm * 8;        // m offset within tile
    const int nb   = wn * 64 + ln * 8;        // n offset within tile

    uint64_t acc[8][4];
#pragma unroll
    for (int i = 0; i < 8; i++)
#pragma unroll
        for (int j = 0; j < 4; j++) acc[i][j] = 0ull;

    auto ldA = [&](int kt, int i) {
        return *(const float4*)(A + (size_t)(m0 + (i >> 2)) * KK + kt * TBK + (i & 3) * 4);
    };
    auto ldB = [&](int kt, int i) {
        return *(const float4*)(B + (size_t)(kt * TBK + (i >> 5)) * N + n0 + (i & 31) * 4);
    };
    gemm_mainloop(As, Bs, ldA, ldB, KK / TBK, tid, aofs, bofs, acc);

    float bn[8];
#pragma unroll
    for (int j = 0; j < 8; j++) bn[j] = __ldg(&bias[n0 + nb + j]);

    float o[8][8];
#pragma unroll
    for (int i = 0; i < 8; i++) {
#pragma unroll
        for (int j = 0; j < 4; j++)
            unpack2(acc[i][j], o[i][2 * j], o[i][2 * j + 1]);
#pragma unroll
        for (int j = 0; j < 8; j++) o[i][j] += bn[j];
    }

    if (mode == 0) {
#pragma unroll
        for (int i = 0; i < 8; i++) {
            float* crow = C + (size_t)(m0 + mb + i) * N + n0 + nb;
            *(float4*)(crow)     = make_float4(o[i][0], o[i][1], o[i][2], o[i][3]);
            *(float4*)(crow + 4) = make_float4(o[i][4], o[i][5], o[i][6], o[i][7]);
        }
    } else if (mode == 1) {
        // ---- sampling-location transform + gather-meta precompute ----
        // Tile = one full head (128 cols). Thread's 8 cols sit in one level.
        __syncthreads();
        float* rps = As;                       // 128 x 8 floats = 4 KB
        {
            int row = tid >> 1, half = tid & 1;
            *(float4*)(rps + row * 8 + half * 4) =
                *(const float4*)(refp + (size_t)(m0 + row) * 8 + half * 4);
        }
        __syncthreads();

        const int h = gx;
        const int lvl = wn * 2 + (ln >> 2);    // thread-uniform level
        const int W = c_W[lvl], H = c_H[lvl];
        const float fW = (float)W, fH = (float)H;
        const float invW = c_invW[lvl], invH = c_invH[lvl];
        const int cstE = c_start[lvl] * EMBED;
        const int pbase = (ln & 3) * 4;        // first point index in level

#pragma unroll
        for (int i = 0; i < 8; i++) {
            const int bq = m0 + mb + i;
            const float* rp = rps + (mb + i) * 8;
            float rx0 = rp[0], rx1 = rp[1], rx2 = rp[2], rx3 = rp[3];
            float ry0 = rp[4], ry1 = rp[5], ry2 = rp[6], ry3 = rp[7];
            float res[8];
#pragma unroll
            for (int j = 0; j < 8; j++) {
                int p = pbase + (j >> 1);
                int c = j & 1;
                float lam = (float)p * (1.0f / 15.0f);
                float pnt = c ? (((ry0 * lam + ry1) * lam + ry2) * lam + ry3)
                              : (((rx0 * lam + rx1) * lam + rx2) * lam + rx3);
                float inv = c ? invH : invW;
                res[j] = pnt + o[i][j] * inv;
            }
            float* crow = C + (size_t)bq * N + n0 + nb;
            *(float4*)(crow)     = make_float4(res[0], res[1], res[2], res[3]);
            *(float4*)(crow + 4) = make_float4(res[4], res[5], res[6], res[7]);

            float2* mbase = meta + ((size_t)(bq * NH + h) * 64) * 4;
#pragma unroll
            for (int j = 0; j < 8; j += 2) {
                int p = pbase + (j >> 1);
                int sp = lvl * NP + p;

                float x = res[j]     * fW - 0.5f;
                float y = res[j + 1] * fH - 0.5f;
                float x0f = floorf(x);
                float y0f = floorf(y);
                float wx = x - x0f;
                float wy = y - y0f;
                int x0 = (int)x0f, y0 = (int)y0f;
                int x1 = x0 + 1,   y1 = y0 + 1;

                bool vx0 = (x0 >= 0) & (x0 < W);
                bool vx1 = (x1 >= 0) & (x1 < W);
                bool vy0 = (y0 >= 0) & (y0 < H);
                bool vy1 = (y1 >= 0) & (y1 < H);

                float w00 = (vx0 & vy0) ? (1.0f - wx) * (1.0f - wy) : 0.0f;
                float w10 = (vx1 & vy0) ? wx * (1.0f - wy)          : 0.0f;
                float w01 = (vx0 & vy1) ? (1.0f - wx) * wy          : 0.0f;
                float w11 = (vx1 & vy1) ? wx * wy                   : 0.0f;

                int cx0 = min(max(x0, 0), W - 1);
                int cx1 = min(max(x1, 0), W - 1);
                int cy0 = min(max(y0, 0), H - 1);
                int cy1 = min(max(y1, 0), H - 1);

                int i00 = cstE + (cy0 * W + cx0) * EMBED;
                int i10 = cstE + (cy0 * W + cx1) * EMBED;
                int i01 = cstE + (cy1 * W + cx0) * EMBED;
                int i11 = cstE + (cy1 * W + cx1) * EMBED;

                float4* mp = (float4*)(mbase + sp * 4);
                mp[0] = make_float4(__int_as_float(i00), w00,
                                    __int_as_float(i10), w10);
                mp[1] = make_float4(__int_as_float(i01), w01,
                                    __int_as_float(i11), w11);
            }
        }
    } else {
        // ---- softmax: head block = wn (64 cols), warp-local over ln ----
#pragma unroll
        for (int i = 0; i < 8; i++) {
            float mx = o[i][0];
#pragma unroll
            for (int j = 1; j < 8; j++) mx = fmaxf(mx, o[i][j]);
            mx = fmaxf(mx, __shfl_xor_sync(0xFFFFFFFFu, mx, 4));
            mx = fmaxf(mx, __shfl_xor_sync(0xFFFFFFFFu, mx, 8));
            mx = fmaxf(mx, __shfl_xor_sync(0xFFFFFFFFu, mx, 16));

            float e[8];
            float s = 0.0f;
#pragma unroll
            for (int j = 0; j < 8; j++) { e[j] = expf(o[i][j] - mx); s += e[j]; }
            s += __shfl_xor_sync(0xFFFFFFFFu, s, 4);
            s += __shfl_xor_sync(0xFFFFFFFFu, s, 8);
            s += __shfl_xor_sync(0xFFFFFFFFu, s, 16);
            float inv = 1.0f / s;

            float* crow = C + (size_t)(m0 + mb + i) * N + n0 + nb;
            *(float4*)(crow)     = make_float4(e[0]*inv, e[1]*inv, e[2]*inv, e[3]*inv);
            *(float4*)(crow + 4) = make_float4(e[4]*inv, e[5]*inv, e[6]*inv, e[7]*inv);
        }
    }
}

// ---------------------------------------------------------------------------
// Output projection GEMM (mode-0 only, same mapping).
// ---------------------------------------------------------------------------
__global__ __launch_bounds__(256, 2) void gemm_out(
    const float* __restrict__ A, const float* __restrict__ B,
    const float* __restrict__ bias, float* __restrict__ C,
    int M, int N, int K)
{
    __shared__ __align__(16) char smem_raw[SMEM_BYTES];
    float* As = (float*)smem_raw;
    float* Bs = As + 2 * (TBK * SA);

    const int tid  = threadIdx.x;
    const int lane = tid & 31;
    const int wid  = tid >> 5;
    const int wm   = wid & 3;
    const int wn   = wid >> 2;
    const int lm   = lane & 3;
    const int ln   = lane >> 2;
    const int m0   = blockIdx.y * TBM;
    const int n0   = blockIdx.x * 128;

    const int aofs = wm * 32 + lm * 8;
    const int bofs = (wn * 8 + ln) * 12;
    const int mb   = wm * 32 + lm * 8;
    const int nb   = wn * 64 + ln * 8;

    uint64_t acc[8][4];
#pragma unroll
    for (int i = 0; i < 8; i++)
#pragma unroll
        for (int j = 0; j < 4; j++) acc[i][j] = 0ull;

    auto ldA = [&](int kt, int i) {
        return *(const float4*)(A + (size_t)(m0 + (i >> 2)) * K + kt * TBK + (i & 3) * 4);
    };
    auto ldB = [&](int kt, int i) {
        return *(const float4*)(B + (size_t)(kt * TBK + (i >> 5)) * N + n0 + (i & 31) * 4);
    };
    gemm_mainloop(As, Bs, ldA, ldB, K / TBK, tid, aofs, bofs, acc);

    float bn[8];
#pragma unroll
    for (int j = 0; j < 8; j++) bn[j] = __ldg(&bias[n0 + nb + j]);

#pragma unroll
    for (int i = 0; i < 8; i++) {
        float o[8];
#pragma unroll
        for (int j = 0; j < 4; j++)
            unpack2(acc[i][j], o[2 * j], o[2 * j + 1]);
#pragma unroll
        for (int j = 0; j < 8; j++) o[j] += bn[j];
        float* crow = C + (size_t)(m0 + mb + i) * N + n0 + nb;
        *(float4*)(crow)     = make_float4(o[0], o[1], o[2], o[3]);
        *(float4*)(crow + 4) = make_float4(o[4], o[5], o[6], o[7]);
    }
}

// ---------------------------------------------------------------------------
// Branchless gather: warp per (b,q,h); lane = (corner, channel-group).
// ---------------------------------------------------------------------------
__global__ __launch_bounds__(256) void gather_kernel(
    const float* __restrict__ v,
    const float2* __restrict__ meta,
    const float* __restrict__ attn,
    float* __restrict__ out)
{
    const int bq = blockIdx.x;
    const int b = bq >> 10;
    const int h = threadIdx.x >> 5;
    const int lane = threadIdx.x & 31;
    const int corner = lane >> 3;
    const int cg = lane & 7;

    const float2* mh = meta + ((size_t)(bq * NH + h) * 64) * 4 + corner;
    const float*  ah = attn + ((size_t)bq * NH + h) * 64;
    const float*  vb = v + (size_t)b * LEN_V * EMBED + h * HD + cg * 4;

    float4 acc = make_float4(0.f, 0.f, 0.f, 0.f);

#pragma unroll 8
    for (int sp = 0; sp < 64; sp++) {
        float2 mw = __ldg(&mh[sp * 4]);
        float a = __ldg(&ah[sp]);
        int idx = __float_as_int(mw.x);
        float4 vv = *(const float4*)(vb + idx);
        float w = mw.y * a;
        acc.x = fmaf(w, vv.x, acc.x);
        acc.y = fmaf(w, vv.y, acc.y);
        acc.z = fmaf(w, vv.z, acc.z);
        acc.w = fmaf(w, vv.w, acc.w);
    }

#pragma unroll
    for (int off = 8; off <= 16; off <<= 1) {
        acc.x += __shfl_xor_sync(0xFFFFFFFFu, acc.x, off);
        acc.y += __shfl_xor_sync(0xFFFFFFFFu, acc.y, off);
        acc.z += __shfl_xor_sync(0xFFFFFFFFu, acc.z, off);
        acc.w += __shfl_xor_sync(0xFFFFFFFFu, acc.w, off);
    }

    if (lane < 8) {
        float* orow = out + ((size_t)bq * NH + h) * HD + cg * 4;
        *(float4*)orow = acc;
    }
}

// ---------------------------------------------------------------------------
// Launch
// ---------------------------------------------------------------------------
extern "C" void kernel_launch(void* const* d_in, const int* in_sizes, int n_in,
                              void* d_out, int out_size)
{
    const float* query  = (const float*)d_in[0];
    const float* refp   = (const float*)d_in[1];
    const float* value  = (const float*)d_in[2];
    const float* W_val  = (const float*)d_in[3];
    const float* b_val  = (const float*)d_in[4];
    const float* W_off  = (const float*)d_in[5];
    const float* b_off  = (const float*)d_in[6];
    const float* W_attn = (const float*)d_in[7];
    const float* b_attn = (const float*)d_in[8];
    const float* W_out  = (const float*)d_in[9];
    const float* b_out  = (const float*)d_in[10];

    float* out  = (float*)d_out;
    float* loc  = out + LOC_OFFSET;
    float* attn = out + ATTN_OFFSET;

    float* gv;
    float* gmid;
    float2* gmeta;
    cudaGetSymbolAddress((void**)&gv, g_v);
    cudaGetSymbolAddress((void**)&gmid, g_mid);
    cudaGetSymbolAddress((void**)&gmeta, g_meta);

    // 1. all three front GEMMs in one launch (724 CTAs)
    mega_gemm<<<MEGA_CTAS, 256>>>(query, value, W_val, b_val, W_off, b_off,
                                  W_attn, b_attn, refp, gv, loc, attn, gmeta);

    // 2. branchless bilinear gather
    gather_kernel<<<BS * LQ, 256>>>(gv, gmeta, attn, gmid);

    // 3. output projection (2 x 32 = 64 CTAs)
    {
        dim3 grid(EMBED / 128, (BS * LQ) / TBM);
        gemm_out<<<grid, 256>>>(gmid, W_out, b_out, out, BS * LQ, EMBED, EMBED);
    }
}

// round 12
// speedup vs baseline: 1.3036x; 1.0297x over previous
#include <cuda_runtime.h>
#include <cstdint>

// ---------------------------------------------------------------------------
// Problem constants
// ---------------------------------------------------------------------------
#define BS 4
#define LQ 1024
#define EMBED 256
#define NH 8
#define NL 4
#define NP 16
#define HD 32
#define LEN_V 5440

#define OUT_ELEMS   (BS * LQ * EMBED)
#define LOC_OFFSET  (OUT_ELEMS)
#define LOC_ELEMS   (BS * LQ * NH * NL * NP * 2)
#define ATTN_OFFSET (LOC_OFFSET + LOC_ELEMS)

__constant__ int   c_H[NL]      = {64, 32, 16, 8};
__constant__ int   c_W[NL]      = {64, 32, 16, 8};
__constant__ int   c_start[NL]  = {0, 4096, 5120, 5376};
__constant__ float c_invW[NL]   = {1.0f/64, 1.0f/32, 1.0f/16, 1.0f/8};
__constant__ float c_invH[NL]   = {1.0f/64, 1.0f/32, 1.0f/16, 1.0f/8};

__device__ float  g_v[BS * LEN_V * EMBED];            // projected value ~22.3 MB
__device__ float  g_mid[BS * LQ * EMBED];             // pre-W_out        4 MB
// gather meta, repacked: per (bq,h): 32 sample-pairs x 4 corners x float4
// float4 = (idx_even, w_even, idx_odd, w_odd); one 64B line per pair.
__device__ float4 g_meta[BS * LQ * NH * 32 * 4];      // ~67 MB

// ---------------------------------------------------------------------------
// Packed f32x2 helpers
// ---------------------------------------------------------------------------
__device__ __forceinline__ uint64_t pack2(float x, float y) {
    uint64_t r;
    asm("mov.b64 %0, {%1, %2};" : "=l"(r) : "f"(x), "f"(y));
    return r;
}
__device__ __forceinline__ void unpack2(uint64_t v, float& x, float& y) {
    asm("mov.b64 {%0, %1}, %2;" : "=f"(x), "=f"(y) : "l"(v));
}
__device__ __forceinline__ void ffma2(uint64_t& d, uint64_t a, uint64_t b) {
    asm("fma.rn.f32x2 %0, %1, %2, %0;" : "+l"(d) : "l"(a), "l"(b));
}

// ---------------------------------------------------------------------------
// Mega GEMM tiling (unchanged from R11): 128x128xBK16, 256 thr, 8x8 microtile.
// ---------------------------------------------------------------------------
#define TBK 16
#define SA  132           // A row stride (m + pad)
#define SB  192           // 16 chunks * 12 floats
#define KK  256

#define SMEM_BYTES ((2 * TBK * SA + 2 * TBK * SB) * 4)   // 41472

#define G3_CTAS 340
#define G1_CTAS 256
#define G2_CTAS 128
#define MEGA_CTAS (G3_CTAS + G1_CTAS + G2_CTAS)

template <typename LdA, typename LdB>
__device__ __forceinline__ void gemm_mainloop(
    float* As, float* Bs, LdA ldA, LdB ldB, int KT,
    int tid, int aofs, int bofs, uint64_t (&acc)[8][4])
{
    auto stage_a = [&](int buf, float4 v, int i) {
        int row = i >> 2, kq = i & 3;
        float* p = As + buf * (TBK * SA) + (kq * 4) * SA + row;
        p[0 * SA] = v.x; p[1 * SA] = v.y; p[2 * SA] = v.z; p[3 * SA] = v.w;
    };
    auto stage_b = [&](int buf, float4 v, int i) {
        int kk = i >> 5, n4 = i & 31;
        *(float4*)(Bs + buf * (TBK * SB) + kk * SB + (n4 >> 1) * 12 + (n4 & 1) * 4) = v;
    };

    stage_a(0, ldA(0, tid), tid);
    stage_a(0, ldA(0, tid + 256), tid + 256);
    stage_b(0, ldB(0, tid), tid);
    stage_b(0, ldB(0, tid + 256), tid + 256);
    __syncthreads();

    int cur = 0;

#pragma unroll 1
    for (int kt = 0; kt < KT; kt++) {
        float4 pa0, pa1, pb0, pb1;
        if (kt + 1 < KT) {
            pa0 = ldA(kt + 1, tid);
            pa1 = ldA(kt + 1, tid + 256);
            pb0 = ldB(kt + 1, tid);
            pb1 = ldB(kt + 1, tid + 256);
        }

#pragma unroll
        for (int k = 0; k < TBK; k++) {
            const float* ap = As + cur * (TBK * SA) + k * SA + aofs;
            float4 a0 = *(const float4*)(ap);
            float4 a1 = *(const float4*)(ap + 4);
            const uint64_t* bp = (const uint64_t*)(Bs + cur * (TBK * SB) + k * SB + bofs);
            uint64_t bd[4];
            bd[0] = bp[0]; bd[1] = bp[1]; bd[2] = bp[2]; bd[3] = bp[3];
            uint64_t ad[8];
            ad[0] = pack2(a0.x, a0.x);
            ad[1] = pack2(a0.y, a0.y);
            ad[2] = pack2(a0.z, a0.z);
            ad[3] = pack2(a0.w, a0.w);
            ad[4] = pack2(a1.x, a1.x);
            ad[5] = pack2(a1.y, a1.y);
            ad[6] = pack2(a1.z, a1.z);
            ad[7] = pack2(a1.w, a1.w);
#pragma unroll
            for (int i = 0; i < 8; i++)
#pragma unroll
                for (int j = 0; j < 4; j++)
                    ffma2(acc[i][j], ad[i], bd[j]);
        }

        if (kt + 1 < KT) {
            const int nxt = cur ^ 1;
            stage_a(nxt, pa0, tid);
            stage_a(nxt, pa1, tid + 256);
            stage_b(nxt, pb0, tid);
            stage_b(nxt, pb1, tid + 256);
            __syncthreads();
            cur = nxt;
        }
    }
}

// ---------------------------------------------------------------------------
// MEGA GEMM: three front GEMMs in one launch.
// ---------------------------------------------------------------------------
__global__ __launch_bounds__(256, 2) void mega_gemm(
    const float* __restrict__ query, const float* __restrict__ value,
    const float* __restrict__ W_val, const float* __restrict__ b_val,
    const float* __restrict__ W_off, const float* __restrict__ b_off,
    const float* __restrict__ W_attn, const float* __restrict__ b_attn,
    const float* __restrict__ refp,
    float* __restrict__ gv, float* __restrict__ loc,
    float* __restrict__ attn_out, float4* __restrict__ meta)
{
    __shared__ __align__(16) char smem_raw[SMEM_BYTES];
    float* As = (float*)smem_raw;
    float* Bs = As + 2 * (TBK * SA);

    const int cta = blockIdx.x;
    const float *A, *B, *bias;
    float* C;
    int N, mode, gx, gy;
    if (cta < G3_CTAS) {
        A = value; B = W_val; bias = b_val; C = gv;
        N = 256; mode = 0; gx = cta & 1; gy = cta >> 1;
    } else if (cta < G3_CTAS + G1_CTAS) {
        int l = cta - G3_CTAS;
        A = query; B = W_off; bias = b_off; C = loc;
        N = 1024; mode = 1; gx = l & 7; gy = l >> 3;
    } else {
        int l = cta - (G3_CTAS + G1_CTAS);
        A = query; B = W_attn; bias = b_attn; C = attn_out;
        N = 512; mode = 2; gx = l & 3; gy = l >> 2;
    }
    const int m0 = gy * 128;
    const int n0 = gx * 128;

    const int tid  = threadIdx.x;
    const int lane = tid & 31;
    const int wid  = tid >> 5;
    const int wm   = wid & 3;
    const int wn   = wid >> 2;
    const int lm   = lane & 3;
    const int ln   = lane >> 2;

    const int aofs = wm * 32 + lm * 8;
    const int bofs = (wn * 8 + ln) * 12;
    const int mb   = wm * 32 + lm * 8;
    const int nb   = wn * 64 + ln * 8;

    uint64_t acc[8][4];
#pragma unroll
    for (int i = 0; i < 8; i++)
#pragma unroll
        for (int j = 0; j < 4; j++) acc[i][j] = 0ull;

    auto ldA = [&](int kt, int i) {
        return *(const float4*)(A + (size_t)(m0 + (i >> 2)) * KK + kt * TBK + (i & 3) * 4);
    };
    auto ldB = [&](int kt, int i) {
        return *(const float4*)(B + (size_t)(kt * TBK + (i >> 5)) * N + n0 + (i & 31) * 4);
    };
    gemm_mainloop(As, Bs, ldA, ldB, KK / TBK, tid, aofs, bofs, acc);

    float bn[8];
#pragma unroll
    for (int j = 0; j < 8; j++) bn[j] = __ldg(&bias[n0 + nb + j]);

    float o[8][8];
#pragma unroll
    for (int i = 0; i < 8; i++) {
#pragma unroll
        for (int j = 0; j < 4; j++)
            unpack2(acc[i][j], o[i][2 * j], o[i][2 * j + 1]);
#pragma unroll
        for (int j = 0; j < 8; j++) o[i][j] += bn[j];
    }

    if (mode == 0) {
#pragma unroll
        for (int i = 0; i < 8; i++) {
            float* crow = C + (size_t)(m0 + mb + i) * N + n0 + nb;
            *(float4*)(crow)     = make_float4(o[i][0], o[i][1], o[i][2], o[i][3]);
            *(float4*)(crow + 4) = make_float4(o[i][4], o[i][5], o[i][6], o[i][7]);
        }
    } else if (mode == 1) {
        // ---- sampling-location transform + gather-meta (pair-corner layout) ----
        __syncthreads();
        float* rps = As;                       // 128 x 8 floats = 4 KB
        {
            int row = tid >> 1, half = tid & 1;
            *(float4*)(rps + row * 8 + half * 4) =
                *(const float4*)(refp + (size_t)(m0 + row) * 8 + half * 4);
        }
        __syncthreads();

        const int h = gx;
        const int lvl = wn * 2 + (ln >> 2);    // thread-uniform level
        const int W = c_W[lvl], H = c_H[lvl];
        const float fW = (float)W, fH = (float)H;
        const float invW = c_invW[lvl], invH = c_invH[lvl];
        const int cstE = c_start[lvl] * EMBED;
        const int pbase = (ln & 3) * 4;        // first point index in level

#pragma unroll
        for (int i = 0; i < 8; i++) {
            const int bq = m0 + mb + i;
            const float* rp = rps + (mb + i) * 8;
            float rx0 = rp[0], rx1 = rp[1], rx2 = rp[2], rx3 = rp[3];
            float ry0 = rp[4], ry1 = rp[5], ry2 = rp[6], ry3 = rp[7];
            float res[8];
#pragma unroll
            for (int j = 0; j < 8; j++) {
                int p = pbase + (j >> 1);
                int c = j & 1;
                float lam = (float)p * (1.0f / 15.0f);
                float pnt = c ? (((ry0 * lam + ry1) * lam + ry2) * lam + ry3)
                              : (((rx0 * lam + rx1) * lam + rx2) * lam + rx3);
                float inv = c ? invH : invW;
                res[j] = pnt + o[i][j] * inv;
            }
            float* crow = C + (size_t)bq * N + n0 + nb;
            *(float4*)(crow)     = make_float4(res[0], res[1], res[2], res[3]);
            *(float4*)(crow + 4) = make_float4(res[4], res[5], res[6], res[7]);

            // gather meta: 4 points -> 2 pairs; per pair, 4 corner float4s
            // cm[corner] for current pair: (idx_e, w_e, idx_o, w_o)
            float4 cm[4];
            float4* mb4 = meta + ((size_t)(bq * NH + h) * 32 + lvl * 8 + (pbase >> 1)) * 4;
#pragma unroll
            for (int t = 0; t < 4; t++) {
                float x = res[2 * t]     * fW - 0.5f;
                float y = res[2 * t + 1] * fH - 0.5f;
                float x0f = floorf(x);
                float y0f = floorf(y);
                float wx = x - x0f;
                float wy = y - y0f;
                int x0 = (int)x0f, y0 = (int)y0f;
                int x1 = x0 + 1,   y1 = y0 + 1;

                bool vx0 = (x0 >= 0) & (x0 < W);
                bool vx1 = (x1 >= 0) & (x1 < W);
                bool vy0 = (y0 >= 0) & (y0 < H);
                bool vy1 = (y1 >= 0) & (y1 < H);

                float w00 = (vx0 & vy0) ? (1.0f - wx) * (1.0f - wy) : 0.0f;
                float w10 = (vx1 & vy0) ? wx * (1.0f - wy)          : 0.0f;
                float w01 = (vx0 & vy1) ? (1.0f - wx) * wy          : 0.0f;
                float w11 = (vx1 & vy1) ? wx * wy                   : 0.0f;

                int cx0 = min(max(x0, 0), W - 1);
                int cx1 = min(max(x1, 0), W - 1);
                int cy0 = min(max(y0, 0), H - 1);
                int cy1 = min(max(y1, 0), H - 1);

                float i00 = __int_as_float(cstE + (cy0 * W + cx0) * EMBED);
                float i10 = __int_as_float(cstE + (cy0 * W + cx1) * EMBED);
                float i01 = __int_as_float(cstE + (cy1 * W + cx0) * EMBED);
                float i11 = __int_as_float(cstE + (cy1 * W + cx1) * EMBED);

                if ((t & 1) == 0) {
                    cm[0].x = i00; cm[0].y = w00;
                    cm[1].x = i10; cm[1].y = w10;
                    cm[2].x = i01; cm[2].y = w01;
                    cm[3].x = i11; cm[3].y = w11;
                } else {
                    cm[0].z = i00; cm[0].w = w00;
                    cm[1].z = i10; cm[1].w = w10;
                    cm[2].z = i01; cm[2].w = w01;
                    cm[3].z = i11; cm[3].w = w11;
                    int pr = t >> 1;
#pragma unroll
                    for (int c = 0; c < 4; c++)
                        mb4[pr * 4 + c] = cm[c];
                }
            }
        }
    } else {
        // ---- softmax: head block = wn (64 cols), warp-local over ln ----
#pragma unroll
        for (int i = 0; i < 8; i++) {
            float mx = o[i][0];
#pragma unroll
            for (int j = 1; j < 8; j++) mx = fmaxf(mx, o[i][j]);
            mx = fmaxf(mx, __shfl_xor_sync(0xFFFFFFFFu, mx, 4));
            mx = fmaxf(mx, __shfl_xor_sync(0xFFFFFFFFu, mx, 8));
            mx = fmaxf(mx, __shfl_xor_sync(0xFFFFFFFFu, mx, 16));

            float e[8];
            float s = 0.0f;
#pragma unroll
            for (int j = 0; j < 8; j++) { e[j] = expf(o[i][j] - mx); s += e[j]; }
            s += __shfl_xor_sync(0xFFFFFFFFu, s, 4);
            s += __shfl_xor_sync(0xFFFFFFFFu, s, 8);
            s += __shfl_xor_sync(0xFFFFFFFFu, s, 16);
            float inv = 1.0f / s;

            float* crow = C + (size_t)(m0 + mb + i) * N + n0 + nb;
            *(float4*)(crow)     = make_float4(e[0]*inv, e[1]*inv, e[2]*inv, e[3]*inv);
            *(float4*)(crow + 4) = make_float4(e[4]*inv, e[5]*inv, e[6]*inv, e[7]*inv);
        }
    }
}

// ---------------------------------------------------------------------------
// Output projection GEMM: 64(M) x 128(N) x BK16 tiles, 256 thr, 4x8 microtile.
// Warp grid 4m x 2n; warp tile 16m x 64n. 128 CTAs (vs 64) halves the
// latency-bound critical path at <1 wave.
// ---------------------------------------------------------------------------
#define OSA 68
#define OSMEM_BYTES ((2 * TBK * OSA + 2 * TBK * SB) * 4)  // 8704 + 24576 = 33280

__global__ __launch_bounds__(256, 3) void gemm_out(
    const float* __restrict__ A, const float* __restrict__ B,
    const float* __restrict__ bias, float* __restrict__ C,
    int M, int N, int K)
{
    __shared__ __align__(16) char smem_raw[OSMEM_BYTES];
    float* As = (float*)smem_raw;
    float* Bs = As + 2 * (TBK * OSA);

    const int tid  = threadIdx.x;
    const int lane = tid & 31;
    const int wid  = tid >> 5;
    const int wm   = wid & 3;
    const int wn   = wid >> 2;
    const int lm   = lane & 3;
    const int ln   = lane >> 2;
    const int m0   = blockIdx.y * 64;
    const int n0   = blockIdx.x * 128;

    const int aofs = wm * 16 + lm * 4;
    const int bofs = (wn * 8 + ln) * 12;
    const int mb   = wm * 16 + lm * 4;
    const int nb   = wn * 64 + ln * 8;

    auto stage_a = [&](int buf, float4 v) {
        int row = tid >> 2, kq = tid & 3;
        float* p = As + buf * (TBK * OSA) + (kq * 4) * OSA + row;
        p[0 * OSA] = v.x; p[1 * OSA] = v.y; p[2 * OSA] = v.z; p[3 * OSA] = v.w;
    };
    auto stage_b = [&](int buf, float4 v, int i) {
        int kk = i >> 5, n4 = i & 31;
        *(float4*)(Bs + buf * (TBK * SB) + kk * SB + (n4 >> 1) * 12 + (n4 & 1) * 4) = v;
    };
    auto ldA = [&](int kt) {
        return *(const float4*)(A + (size_t)(m0 + (tid >> 2)) * K + kt * TBK + (tid & 3) * 4);
    };
    auto ldB = [&](int kt, int i) {
        return *(const float4*)(B + (size_t)(kt * TBK + (i >> 5)) * N + n0 + (i & 31) * 4);
    };

    stage_a(0, ldA(0));
    stage_b(0, ldB(0, tid), tid);
    stage_b(0, ldB(0, tid + 256), tid + 256);
    __syncthreads();

    uint64_t acc[4][4];
#pragma unroll
    for (int i = 0; i < 4; i++)
#pragma unroll
        for (int j = 0; j < 4; j++) acc[i][j] = 0ull;

    int cur = 0;
    const int KT = K / TBK;

#pragma unroll 1
    for (int kt = 0; kt < KT; kt++) {
        float4 pa, pb0, pb1;
        if (kt + 1 < KT) {
            pa  = ldA(kt + 1);
            pb0 = ldB(kt + 1, tid);
            pb1 = ldB(kt + 1, tid + 256);
        }

#pragma unroll
        for (int k = 0; k < TBK; k++) {
            float4 a4 = *(const float4*)(As + cur * (TBK * OSA) + k * OSA + aofs);
            const uint64_t* bp = (const uint64_t*)(Bs + cur * (TBK * SB) + k * SB + bofs);
            uint64_t bd[4];
            bd[0] = bp[0]; bd[1] = bp[1]; bd[2] = bp[2]; bd[3] = bp[3];
            uint64_t ad[4];
            ad[0] = pack2(a4.x, a4.x);
            ad[1] = pack2(a4.y, a4.y);
            ad[2] = pack2(a4.z, a4.z);
            ad[3] = pack2(a4.w, a4.w);
#pragma unroll
            for (int i = 0; i < 4; i++)
#pragma unroll
                for (int j = 0; j < 4; j++)
                    ffma2(acc[i][j], ad[i], bd[j]);
        }

        if (kt + 1 < KT) {
            const int nxt = cur ^ 1;
            stage_a(nxt, pa);
            stage_b(nxt, pb0, tid);
            stage_b(nxt, pb1, tid + 256);
            __syncthreads();
            cur = nxt;
        }
    }

    float bn[8];
#pragma unroll
    for (int j = 0; j < 8; j++) bn[j] = __ldg(&bias[n0 + nb + j]);

#pragma unroll
    for (int i = 0; i < 4; i++) {
        float o[8];
#pragma unroll
        for (int j = 0; j < 4; j++)
            unpack2(acc[i][j], o[2 * j], o[2 * j + 1]);
#pragma unroll
        for (int j = 0; j < 8; j++) o[j] += bn[j];
        float* crow = C + (size_t)(m0 + mb + i) * N + n0 + nb;
        *(float4*)(crow)     = make_float4(o[0], o[1], o[2], o[3]);
        *(float4*)(crow + 4) = make_float4(o[4], o[5], o[6], o[7]);
    }
}

// ---------------------------------------------------------------------------
// Gather v2: warp per (b,q,h); lane = (corner, channel-group).
// 8-sample chunks with explicit load batching (MLP ~8):
//   meta: 1 float4 per 2 samples per lane (64B line covers 4 corners) -> 4 wf/8
//   attn: 2 float4 broadcasts per 8 samples                           -> 2 wf/8
//   v   : 1 LDG.128 per sample (4 lines/warp)                         -> 32 wf/8
// ---------------------------------------------------------------------------
__global__ __launch_bounds__(256) void gather_kernel(
    const float* __restrict__ v,
    const float4* __restrict__ meta,
    const float* __restrict__ attn,
    float* __restrict__ out)
{
    const int bq = blockIdx.x;
    const int b = bq >> 10;
    const int h = threadIdx.x >> 5;
    const int lane = threadIdx.x & 31;
    const int corner = lane >> 3;
    const int cg = lane & 7;

    const float4* m4p = meta + ((size_t)(bq * NH + h) * 32) * 4 + corner;
    const float*  ah  = attn + ((size_t)bq * NH + h) * 64;
    const float*  vb  = v + (size_t)b * LEN_V * EMBED + h * HD + cg * 4;

    float4 acc = make_float4(0.f, 0.f, 0.f, 0.f);

#pragma unroll
    for (int base = 0; base < 64; base += 8) {
        float4 aA = __ldg((const float4*)(ah + base));
        float4 aB = __ldg((const float4*)(ah + base + 4));
        float4 m4[4];
#pragma unroll
        for (int q = 0; q < 4; q++)
            m4[q] = __ldg(&m4p[(base / 2 + q) * 4]);

        float4 vv[8];
#pragma unroll
        for (int q = 0; q < 4; q++) {
            vv[2 * q]     = *(const float4*)(vb + __float_as_int(m4[q].x));
            vv[2 * q + 1] = *(const float4*)(vb + __float_as_int(m4[q].z));
        }

        float a8[8] = {aA.x, aA.y, aA.z, aA.w, aB.x, aB.y, aB.z, aB.w};
#pragma unroll
        for (int q = 0; q < 4; q++) {
            float w0 = m4[q].y * a8[2 * q];
            float w1 = m4[q].w * a8[2 * q + 1];
            acc.x = fmaf(w0, vv[2 * q].x, acc.x);
            acc.y = fmaf(w0, vv[2 * q].y, acc.y);
            acc.z = fmaf(w0, vv[2 * q].z, acc.z);
            acc.w = fmaf(w0, vv[2 * q].w, acc.w);
            acc.x = fmaf(w1, vv[2 * q + 1].x, acc.x);
            acc.y = fmaf(w1, vv[2 * q + 1].y, acc.y);
            acc.z = fmaf(w1, vv[2 * q + 1].z, acc.z);
            acc.w = fmaf(w1, vv[2 * q + 1].w, acc.w);
        }
    }

#pragma unroll
    for (int off = 8; off <= 16; off <<= 1) {
        acc.x += __shfl_xor_sync(0xFFFFFFFFu, acc.x, off);
        acc.y += __shfl_xor_sync(0xFFFFFFFFu, acc.y, off);
        acc.z += __shfl_xor_sync(0xFFFFFFFFu, acc.z, off);
        acc.w += __shfl_xor_sync(0xFFFFFFFFu, acc.w, off);
    }

    if (lane < 8) {
        float* orow = out + ((size_t)bq * NH + h) * HD + cg * 4;
        *(float4*)orow = acc;
    }
}

// ---------------------------------------------------------------------------
// Launch
// ---------------------------------------------------------------------------
extern "C" void kernel_launch(void* const* d_in, const int* in_sizes, int n_in,
                              void* d_out, int out_size)
{
    const float* query  = (const float*)d_in[0];
    const float* refp   = (const float*)d_in[1];
    const float* value  = (const float*)d_in[2];
    const float* W_val  = (const float*)d_in[3];
    const float* b_val  = (const float*)d_in[4];
    const float* W_off  = (const float*)d_in[5];
    const float* b_off  = (const float*)d_in[6];
    const float* W_attn = (const float*)d_in[7];
    const float* b_attn = (const float*)d_in[8];
    const float* W_out  = (const float*)d_in[9];
    const float* b_out  = (const float*)d_in[10];

    float* out  = (float*)d_out;
    float* loc  = out + LOC_OFFSET;
    float* attn = out + ATTN_OFFSET;

    float* gv;
    float* gmid;
    float4* gmeta;
    cudaGetSymbolAddress((void**)&gv, g_v);
    cudaGetSymbolAddress((void**)&gmid, g_mid);
    cudaGetSymbolAddress((void**)&gmeta, g_meta);

    // 1. all three front GEMMs in one launch (724 CTAs)
    mega_gemm<<<MEGA_CTAS, 256>>>(query, value, W_val, b_val, W_off, b_off,
                                  W_attn, b_attn, refp, gv, loc, attn, gmeta);

    // 2. batched branchless gather
    gather_kernel<<<BS * LQ, 256>>>(gv, gmeta, attn, gmid);

    // 3. output projection (2 x 64 = 128 CTAs)
    {
        dim3 grid(EMBED / 128, (BS * LQ) / 64);
        gemm_out<<<grid, 256>>>(gmid, W_out, b_out, out, BS * LQ, EMBED, EMBED);
    }
}

// round 13
// speedup vs baseline: 1.3259x; 1.0171x over previous
#include <cuda_runtime.h>
#include <cstdint>

// ---------------------------------------------------------------------------
// Problem constants
// ---------------------------------------------------------------------------
#define BS 4
#define LQ 1024
#define EMBED 256
#define NH 8
#define NL 4
#define NP 16
#define HD 32
#define LEN_V 5440
#define MQ (BS * LQ)        // 4096
#define MV (BS * LEN_V)     // 21760

#define OUT_ELEMS   (BS * LQ * EMBED)
#define LOC_OFFSET  (OUT_ELEMS)
#define LOC_ELEMS   (BS * LQ * NH * NL * NP * 2)
#define ATTN_OFFSET (LOC_OFFSET + LOC_ELEMS)

__constant__ int   c_H[NL]      = {64, 32, 16, 8};
__constant__ int   c_W[NL]      = {64, 32, 16, 8};
__constant__ int   c_start[NL]  = {0, 4096, 5120, 5376};
__constant__ float c_invW[NL]   = {1.0f/64, 1.0f/32, 1.0f/16, 1.0f/8};
__constant__ float c_invH[NL]   = {1.0f/64, 1.0f/32, 1.0f/16, 1.0f/8};

__device__ float  g_v[MV * EMBED];                    // projected value ~22.3 MB
__device__ float  g_mid[MQ * EMBED];                  // pre-W_out        4 MB
__device__ float4 g_meta[MQ * NH * 32 * 4];           // gather meta     ~67 MB
__device__ float  g_vT[EMBED * MV];                   // value transposed 22.3 MB
__device__ float  g_qT[EMBED * MQ];                   // query transposed  4 MB

// ---------------------------------------------------------------------------
// Packed f32x2 + cp.async helpers
// ---------------------------------------------------------------------------
__device__ __forceinline__ uint64_t pack2(float x, float y) {
    uint64_t r;
    asm("mov.b64 %0, {%1, %2};" : "=l"(r) : "f"(x), "f"(y));
    return r;
}
__device__ __forceinline__ void unpack2(uint64_t v, float& x, float& y) {
    asm("mov.b64 {%0, %1}, %2;" : "=f"(x), "=f"(y) : "l"(v));
}
__device__ __forceinline__ void ffma2(uint64_t& d, uint64_t a, uint64_t b) {
    asm("fma.rn.f32x2 %0, %1, %2, %0;" : "+l"(d) : "l"(a), "l"(b));
}
__device__ __forceinline__ void cp16(void* s, const void* g) {
    uint32_t sa = (uint32_t)__cvta_generic_to_shared(s);
    asm volatile("cp.async.ca.shared.global [%0], [%1], 16;" :: "r"(sa), "l"(g));
}
#define CP_COMMIT() asm volatile("cp.async.commit_group;" ::: "memory")
#define CP_WAIT(N)  asm volatile("cp.async.wait_group %0;" :: "n"(N) : "memory")

// ---------------------------------------------------------------------------
// Transpose kernel: value[MV,256] -> vT[256,MV], query[MQ,256] -> qT[256,MQ]
// 32x32 tiles, 256 threads.
// ---------------------------------------------------------------------------
#define VT_TILES ((MV / 32) * (EMBED / 32))   // 680*8 = 5440
#define QT_TILES ((MQ / 32) * (EMBED / 32))   // 128*8 = 1024

__global__ __launch_bounds__(256) void transpose_kernel(
    const float* __restrict__ value, const float* __restrict__ query,
    float* __restrict__ vT, float* __restrict__ qT)
{
    __shared__ float tile[32][33];
    int t = blockIdx.x;
    const float* src; float* dst; int Mr, tm, tk;
    if (t < VT_TILES) { src = value; dst = vT; Mr = MV; tm = t >> 3; tk = t & 7; }
    else { t -= VT_TILES; src = query; dst = qT; Mr = MQ; tm = t >> 3; tk = t & 7; }

    const int r  = threadIdx.x >> 3;   // 0..31
    const int c4 = threadIdx.x & 7;    // 0..7

    float4 v = *(const float4*)(src + (size_t)(tm * 32 + r) * EMBED + tk * 32 + c4 * 4);
    tile[r][c4 * 4 + 0] = v.x;
    tile[r][c4 * 4 + 1] = v.y;
    tile[r][c4 * 4 + 2] = v.z;
    tile[r][c4 * 4 + 3] = v.w;
    __syncthreads();

    float4 w;
    w.x = tile[c4 * 4 + 0][r];
    w.y = tile[c4 * 4 + 1][r];
    w.z = tile[c4 * 4 + 2][r];
    w.w = tile[c4 * 4 + 3][r];
    *(float4*)(dst + (size_t)(tk * 32 + r) * Mr + tm * 32 + c4 * 4) = w;
}

// ---------------------------------------------------------------------------
// MEGA GEMM with cp.async 3-stage pipeline.
// Tiling: 128x128xBK16, 256 thr, microtile 8x8 (warp 4m x 2n, lm=lane&3, ln=lane>>2).
// A comes from pre-transposed A_T[k][m]: every staged chunk is contiguous 16B.
// ---------------------------------------------------------------------------
#define TBK  16
#define SAm  128                       // A stage row stride (floats)
#define SBm  192                       // B: 16 chunks * 12 floats
#define STGA (TBK * SAm)               // 2048 floats
#define STGB (TBK * SBm)               // 3072 floats
#define MEGA_SMEM (3 * (STGA + STGB) * 4)   // 61440 B
#define KK   256

#define G3_CTAS 340
#define G1_CTAS 256
#define G2_CTAS 128
#define MEGA_CTAS (G3_CTAS + G1_CTAS + G2_CTAS)

__global__ __launch_bounds__(256, 2) void mega_gemm(
    const float* __restrict__ vT, const float* __restrict__ qT,
    const float* __restrict__ W_val, const float* __restrict__ b_val,
    const float* __restrict__ W_off, const float* __restrict__ b_off,
    const float* __restrict__ W_attn, const float* __restrict__ b_attn,
    const float* __restrict__ refp,
    float* __restrict__ gv, float* __restrict__ loc,
    float* __restrict__ attn_out, float4* __restrict__ meta)
{
    extern __shared__ __align__(16) float smem[];
    float* As = smem;                  // 3 stages x STGA
    float* Bs = smem + 3 * STGA;       // 3 stages x STGB

    const int cta = blockIdx.x;
    const float *AT, *B, *bias;
    float* C;
    int N, mode, gx, gy, Mlen;
    if (cta < G3_CTAS) {
        AT = vT; Mlen = MV; B = W_val; bias = b_val; C = gv;
        N = 256; mode = 0; gx = cta & 1; gy = cta >> 1;
    } else if (cta < G3_CTAS + G1_CTAS) {
        int l = cta - G3_CTAS;
        AT = qT; Mlen = MQ; B = W_off; bias = b_off; C = loc;
        N = 1024; mode = 1; gx = l & 7; gy = l >> 3;
    } else {
        int l = cta - (G3_CTAS + G1_CTAS);
        AT = qT; Mlen = MQ; B = W_attn; bias = b_attn; C = attn_out;
        N = 512; mode = 2; gx = l & 3; gy = l >> 2;
    }
    const int m0 = gy * 128;
    const int n0 = gx * 128;

    const int tid  = threadIdx.x;
    const int lane = tid & 31;
    const int wid  = tid >> 5;
    const int wm   = wid & 3;
    const int wn   = wid >> 2;
    const int lm   = lane & 3;
    const int ln   = lane >> 2;

    const int aofs = wm * 32 + lm * 8;
    const int bofs = (wn * 8 + ln) * 12;
    const int mb   = wm * 32 + lm * 8;
    const int nb   = wn * 64 + ln * 8;

    // ---- async tile stager ----
    auto stage = [&](int sg, int kt) {
        const int k0 = kt * TBK;
#pragma unroll
        for (int r2 = 0; r2 < 2; r2++) {
            int i = tid + r2 * 256;
            int k = i >> 5, m4 = i & 31;
            cp16(As + sg * STGA + k * SAm + m4 * 4,
                 AT + (size_t)(k0 + k) * Mlen + m0 + m4 * 4);
        }
#pragma unroll
        for (int r2 = 0; r2 < 2; r2++) {
            int i = tid + r2 * 256;
            int kk = i >> 5, n4 = i & 31;
            cp16(Bs + sg * STGB + kk * SBm + (n4 >> 1) * 12 + (n4 & 1) * 4,
                 B + (size_t)(k0 + kk) * N + n0 + n4 * 4);
        }
    };

    stage(0, 0); CP_COMMIT();
    stage(1, 1); CP_COMMIT();

    uint64_t acc[8][4];
#pragma unroll
    for (int i = 0; i < 8; i++)
#pragma unroll
        for (int j = 0; j < 4; j++) acc[i][j] = 0ull;

    const int KT = KK / TBK;   // 16
    int cur = 0;

#pragma unroll 1
    for (int kt = 0; kt < KT; kt++) {
        if (kt + 1 < KT) { CP_WAIT(1); } else { CP_WAIT(0); }
        __syncthreads();
        if (kt + 2 < KT) {
            int sg = kt + 2; sg -= (sg >= 3) ? 3 : 0; sg -= (sg >= 3) ? 3 : 0;
            // (kt+2)%3 without division:
            sg = (kt + 2) % 3;
            stage(sg, kt + 2);
            CP_COMMIT();
        }

#pragma unroll
        for (int k = 0; k < TBK; k++) {
            const float* ap = As + cur * STGA + k * SAm + aofs;
            float4 a0 = *(const float4*)(ap);
            float4 a1 = *(const float4*)(ap + 4);
            const uint64_t* bp = (const uint64_t*)(Bs + cur * STGB + k * SBm + bofs);
            uint64_t bd[4];
            bd[0] = bp[0]; bd[1] = bp[1]; bd[2] = bp[2]; bd[3] = bp[3];
            uint64_t ad[8];
            ad[0] = pack2(a0.x, a0.x);
            ad[1] = pack2(a0.y, a0.y);
            ad[2] = pack2(a0.z, a0.z);
            ad[3] = pack2(a0.w, a0.w);
            ad[4] = pack2(a1.x, a1.x);
            ad[5] = pack2(a1.y, a1.y);
            ad[6] = pack2(a1.z, a1.z);
            ad[7] = pack2(a1.w, a1.w);
#pragma unroll
            for (int i = 0; i < 8; i++)
#pragma unroll
                for (int j = 0; j < 4; j++)
                    ffma2(acc[i][j], ad[i], bd[j]);
        }

        cur++;
        if (cur == 3) cur = 0;
    }

    float bn[8];
#pragma unroll
    for (int j = 0; j < 8; j++) bn[j] = __ldg(&bias[n0 + nb + j]);

    float o[8][8];
#pragma unroll
    for (int i = 0; i < 8; i++) {
#pragma unroll
        for (int j = 0; j < 4; j++)
            unpack2(acc[i][j], o[i][2 * j], o[i][2 * j + 1]);
#pragma unroll
        for (int j = 0; j < 8; j++) o[i][j] += bn[j];
    }

    if (mode == 0) {
#pragma unroll
        for (int i = 0; i < 8; i++) {
            float* crow = C + (size_t)(m0 + mb + i) * N + n0 + nb;
            *(float4*)(crow)     = make_float4(o[i][0], o[i][1], o[i][2], o[i][3]);
            *(float4*)(crow + 4) = make_float4(o[i][4], o[i][5], o[i][6], o[i][7]);
        }
    } else if (mode == 1) {
        // ---- sampling-location transform + gather-meta (pair-corner layout) ----
        __syncthreads();
        float* rps = As;                       // 128 x 8 floats = 4 KB
        {
            int row = tid >> 1, half = tid & 1;
            *(float4*)(rps + row * 8 + half * 4) =
                *(const float4*)(refp + (size_t)(m0 + row) * 8 + half * 4);
        }
        __syncthreads();

        const int h = gx;
        const int lvl = wn * 2 + (ln >> 2);    // thread-uniform level
        const int W = c_W[lvl], H = c_H[lvl];
        const float fW = (float)W, fH = (float)H;
        const float invW = c_invW[lvl], invH = c_invH[lvl];
        const int cstE = c_start[lvl] * EMBED;
        const int pbase = (ln & 3) * 4;        // first point index in level

#pragma unroll
        for (int i = 0; i < 8; i++) {
            const int bq = m0 + mb + i;
            const float* rp = rps + (mb + i) * 8;
            float rx0 = rp[0], rx1 = rp[1], rx2 = rp[2], rx3 = rp[3];
            float ry0 = rp[4], ry1 = rp[5], ry2 = rp[6], ry3 = rp[7];
            float res[8];
#pragma unroll
            for (int j = 0; j < 8; j++) {
                int p = pbase + (j >> 1);
                int c = j & 1;
                float lam = (float)p * (1.0f / 15.0f);
                float pnt = c ? (((ry0 * lam + ry1) * lam + ry2) * lam + ry3)
                              : (((rx0 * lam + rx1) * lam + rx2) * lam + rx3);
                float inv = c ? invH : invW;
                res[j] = pnt + o[i][j] * inv;
            }
            float* crow = C + (size_t)bq * N + n0 + nb;
            *(float4*)(crow)     = make_float4(res[0], res[1], res[2], res[3]);
            *(float4*)(crow + 4) = make_float4(res[4], res[5], res[6], res[7]);

            float4 cm[4];
            float4* mb4 = meta + ((size_t)(bq * NH + h) * 32 + lvl * 8 + (pbase >> 1)) * 4;
#pragma unroll
            for (int t = 0; t < 4; t++) {
                float x = res[2 * t]     * fW - 0.5f;
                float y = res[2 * t + 1] * fH - 0.5f;
                float x0f = floorf(x);
                float y0f = floorf(y);
                float wx = x - x0f;
                float wy = y - y0f;
                int x0 = (int)x0f, y0 = (int)y0f;
                int x1 = x0 + 1,   y1 = y0 + 1;

                bool vx0 = (x0 >= 0) & (x0 < W);
                bool vx1 = (x1 >= 0) & (x1 < W);
                bool vy0 = (y0 >= 0) & (y0 < H);
                bool vy1 = (y1 >= 0) & (y1 < H);

                float w00 = (vx0 & vy0) ? (1.0f - wx) * (1.0f - wy) : 0.0f;
                float w10 = (vx1 & vy0) ? wx * (1.0f - wy)          : 0.0f;
                float w01 = (vx0 & vy1) ? (1.0f - wx) * wy          : 0.0f;
                float w11 = (vx1 & vy1) ? wx * wy                   : 0.0f;

                int cx0 = min(max(x0, 0), W - 1);
                int cx1 = min(max(x1, 0), W - 1);
                int cy0 = min(max(y0, 0), H - 1);
                int cy1 = min(max(y1, 0), H - 1);

                float i00 = __int_as_float(cstE + (cy0 * W + cx0) * EMBED);
                float i10 = __int_as_float(cstE + (cy0 * W + cx1) * EMBED);
                float i01 = __int_as_float(cstE + (cy1 * W + cx0) * EMBED);
                float i11 = __int_as_float(cstE + (cy1 * W + cx1) * EMBED);

                if ((t & 1) == 0) {
                    cm[0].x = i00; cm[0].y = w00;
                    cm[1].x = i10; cm[1].y = w10;
                    cm[2].x = i01; cm[2].y = w01;
                    cm[3].x = i11; cm[3].y = w11;
                } else {
                    cm[0].z = i00; cm[0].w = w00;
                    cm[1].z = i10; cm[1].w = w10;
                    cm[2].z = i01; cm[2].w = w01;
                    cm[3].z = i11; cm[3].w = w11;
                    int pr = t >> 1;
#pragma unroll
                    for (int c = 0; c < 4; c++)
                        mb4[pr * 4 + c] = cm[c];
                }
            }
        }
    } else {
        // ---- softmax: head block = wn (64 cols), warp-local over ln ----
#pragma unroll
        for (int i = 0; i < 8; i++) {
            float mx = o[i][0];
#pragma unroll
            for (int j = 1; j < 8; j++) mx = fmaxf(mx, o[i][j]);
            mx = fmaxf(mx, __shfl_xor_sync(0xFFFFFFFFu, mx, 4));
            mx = fmaxf(mx, __shfl_xor_sync(0xFFFFFFFFu, mx, 8));
            mx = fmaxf(mx, __shfl_xor_sync(0xFFFFFFFFu, mx, 16));

            float e[8];
            float s = 0.0f;
#pragma unroll
            for (int j = 0; j < 8; j++) { e[j] = expf(o[i][j] - mx); s += e[j]; }
            s += __shfl_xor_sync(0xFFFFFFFFu, s, 4);
            s += __shfl_xor_sync(0xFFFFFFFFu, s, 8);
            s += __shfl_xor_sync(0xFFFFFFFFu, s, 16);
            float inv = 1.0f / s;

            float* crow = C + (size_t)(m0 + mb + i) * N + n0 + nb;
            *(float4*)(crow)     = make_float4(e[0]*inv, e[1]*inv, e[2]*inv, e[3]*inv);
            *(float4*)(crow + 4) = make_float4(e[4]*inv, e[5]*inv, e[6]*inv, e[7]*inv);
        }
    }
}

// ---------------------------------------------------------------------------
// Output projection GEMM (unchanged from R12): 64x128xBK16, 4x8 microtile.
// ---------------------------------------------------------------------------
#define OSA 68
#define OSB 192
#define OSMEM_BYTES ((2 * TBK * OSA + 2 * TBK * OSB) * 4)

__global__ __launch_bounds__(256, 3) void gemm_out(
    const float* __restrict__ A, const float* __restrict__ B,
    const float* __restrict__ bias, float* __restrict__ C,
    int M, int N, int K)
{
    __shared__ __align__(16) char smem_raw[OSMEM_BYTES];
    float* As = (float*)smem_raw;
    float* Bs = As + 2 * (TBK * OSA);

    const int tid  = threadIdx.x;
    const int lane = tid & 31;
    const int wid  = tid >> 5;
    const int wm   = wid & 3;
    const int wn   = wid >> 2;
    const int lm   = lane & 3;
    const int ln   = lane >> 2;
    const int m0   = blockIdx.y * 64;
    const int n0   = blockIdx.x * 128;

    const int aofs = wm * 16 + lm * 4;
    const int bofs = (wn * 8 + ln) * 12;
    const int mb   = wm * 16 + lm * 4;
    const int nb   = wn * 64 + ln * 8;

    auto stage_a = [&](int buf, float4 v) {
        int row = tid >> 2, kq = tid & 3;
        float* p = As + buf * (TBK * OSA) + (kq * 4) * OSA + row;
        p[0 * OSA] = v.x; p[1 * OSA] = v.y; p[2 * OSA] = v.z; p[3 * OSA] = v.w;
    };
    auto stage_b = [&](int buf, float4 v, int i) {
        int kk = i >> 5, n4 = i & 31;
        *(float4*)(Bs + buf * (TBK * OSB) + kk * OSB + (n4 >> 1) * 12 + (n4 & 1) * 4) = v;
    };
    auto ldA = [&](int kt) {
        return *(const float4*)(A + (size_t)(m0 + (tid >> 2)) * K + kt * TBK + (tid & 3) * 4);
    };
    auto ldB = [&](int kt, int i) {
        return *(const float4*)(B + (size_t)(kt * TBK + (i >> 5)) * N + n0 + (i & 31) * 4);
    };

    stage_a(0, ldA(0));
    stage_b(0, ldB(0, tid), tid);
    stage_b(0, ldB(0, tid + 256), tid + 256);
    __syncthreads();

    uint64_t acc[4][4];
#pragma unroll
    for (int i = 0; i < 4; i++)
#pragma unroll
        for (int j = 0; j < 4; j++) acc[i][j] = 0ull;

    int cur = 0;
    const int KT = K / TBK;

#pragma unroll 1
    for (int kt = 0; kt < KT; kt++) {
        float4 pa, pb0, pb1;
        if (kt + 1 < KT) {
            pa  = ldA(kt + 1);
            pb0 = ldB(kt + 1, tid);
            pb1 = ldB(kt + 1, tid + 256);
        }

#pragma unroll
        for (int k = 0; k < TBK; k++) {
            float4 a4 = *(const float4*)(As + cur * (TBK * OSA) + k * OSA + aofs);
            const uint64_t* bp = (const uint64_t*)(Bs + cur * (TBK * OSB) + k * OSB + bofs);
            uint64_t bd[4];
            bd[0] = bp[0]; bd[1] = bp[1]; bd[2] = bp[2]; bd[3] = bp[3];
            uint64_t ad[4];
            ad[0] = pack2(a4.x, a4.x);
            ad[1] = pack2(a4.y, a4.y);
            ad[2] = pack2(a4.z, a4.z);
            ad[3] = pack2(a4.w, a4.w);
#pragma unroll
            for (int i = 0; i < 4; i++)
#pragma unroll
                for (int j = 0; j < 4; j++)
                    ffma2(acc[i][j], ad[i], bd[j]);
        }

        if (kt + 1 < KT) {
            const int nxt = cur ^ 1;
            stage_a(nxt, pa);
            stage_b(nxt, pb0, tid);
            stage_b(nxt, pb1, tid + 256);
            __syncthreads();
            cur = nxt;
        }
    }

    float bn[8];
#pragma unroll
    for (int j = 0; j < 8; j++) bn[j] = __ldg(&bias[n0 + nb + j]);

#pragma unroll
    for (int i = 0; i < 4; i++) {
        float o[8];
#pragma unroll
        for (int j = 0; j < 4; j++)
            unpack2(acc[i][j], o[2 * j], o[2 * j + 1]);
#pragma unroll
        for (int j = 0; j < 8; j++) o[j] += bn[j];
        float* crow = C + (size_t)(m0 + mb + i) * N + n0 + nb;
        *(float4*)(crow)     = make_float4(o[0], o[1], o[2], o[3]);
        *(float4*)(crow + 4) = make_float4(o[4], o[5], o[6], o[7]);
    }
}

// ---------------------------------------------------------------------------
// Gather (unchanged from R12): warp per (b,q,h); 8-sample batches.
// ---------------------------------------------------------------------------
__global__ __launch_bounds__(256) void gather_kernel(
    const float* __restrict__ v,
    const float4* __restrict__ meta,
    const float* __restrict__ attn,
    float* __restrict__ out)
{
    const int bq = blockIdx.x;
    const int b = bq >> 10;
    const int h = threadIdx.x >> 5;
    const int lane = threadIdx.x & 31;
    const int corner = lane >> 3;
    const int cg = lane & 7;

    const float4* m4p = meta + ((size_t)(bq * NH + h) * 32) * 4 + corner;
    const float*  ah  = attn + ((size_t)bq * NH + h) * 64;
    const float*  vb  = v + (size_t)b * LEN_V * EMBED + h * HD + cg * 4;

    float4 acc = make_float4(0.f, 0.f, 0.f, 0.f);

#pragma unroll
    for (int base = 0; base < 64; base += 8) {
        float4 aA = __ldg((const float4*)(ah + base));
        float4 aB = __ldg((const float4*)(ah + base + 4));
        float4 m4[4];
#pragma unroll
        for (int q = 0; q < 4; q++)
            m4[q] = __ldg(&m4p[(base / 2 + q) * 4]);

        float4 vv[8];
#pragma unroll
        for (int q = 0; q < 4; q++) {
            vv[2 * q]     = *(const float4*)(vb + __float_as_int(m4[q].x));
            vv[2 * q + 1] = *(const float4*)(vb + __float_as_int(m4[q].z));
        }

        float a8[8] = {aA.x, aA.y, aA.z, aA.w, aB.x, aB.y, aB.z, aB.w};
#pragma unroll
        for (int q = 0; q < 4; q++) {
            float w0 = m4[q].y * a8[2 * q];
            float w1 = m4[q].w * a8[2 * q + 1];
            acc.x = fmaf(w0, vv[2 * q].x, acc.x);
            acc.y = fmaf(w0, vv[2 * q].y, acc.y);
            acc.z = fmaf(w0, vv[2 * q].z, acc.z);
            acc.w = fmaf(w0, vv[2 * q].w, acc.w);
            acc.x = fmaf(w1, vv[2 * q + 1].x, acc.x);
            acc.y = fmaf(w1, vv[2 * q + 1].y, acc.y);
            acc.z = fmaf(w1, vv[2 * q + 1].z, acc.z);
            acc.w = fmaf(w1, vv[2 * q + 1].w, acc.w);
        }
    }

#pragma unroll
    for (int off = 8; off <= 16; off <<= 1) {
        acc.x += __shfl_xor_sync(0xFFFFFFFFu, acc.x, off);
        acc.y += __shfl_xor_sync(0xFFFFFFFFu, acc.y, off);
        acc.z += __shfl_xor_sync(0xFFFFFFFFu, acc.z, off);
        acc.w += __shfl_xor_sync(0xFFFFFFFFu, acc.w, off);
    }

    if (lane < 8) {
        float* orow = out + ((size_t)bq * NH + h) * HD + cg * 4;
        *(float4*)orow = acc;
    }
}

// ---------------------------------------------------------------------------
// Launch
// ---------------------------------------------------------------------------
extern "C" void kernel_launch(void* const* d_in, const int* in_sizes, int n_in,
                              void* d_out, int out_size)
{
    const float* query  = (const float*)d_in[0];
    const float* refp   = (const float*)d_in[1];
    const float* value  = (const float*)d_in[2];
    const float* W_val  = (const float*)d_in[3];
    const float* b_val  = (const float*)d_in[4];
    const float* W_off  = (const float*)d_in[5];
    const float* b_off  = (const float*)d_in[6];
    const float* W_attn = (const float*)d_in[7];
    const float* b_attn = (const float*)d_in[8];
    const float* W_out  = (const float*)d_in[9];
    const float* b_out  = (const float*)d_in[10];

    float* out  = (float*)d_out;
    float* loc  = out + LOC_OFFSET;
    float* attn = out + ATTN_OFFSET;

    float* gv;
    float* gmid;
    float4* gmeta;
    float* gvT;
    float* gqT;
    cudaGetSymbolAddress((void**)&gv, g_v);
    cudaGetSymbolAddress((void**)&gmid, g_mid);
    cudaGetSymbolAddress((void**)&gmeta, g_meta);
    cudaGetSymbolAddress((void**)&gvT, g_vT);
    cudaGetSymbolAddress((void**)&gqT, g_qT);

    cudaFuncSetAttribute(mega_gemm,
                         cudaFuncAttributeMaxDynamicSharedMemorySize, MEGA_SMEM);

    // 0. one-shot transpose of value + query (k-major A operands)
    transpose_kernel<<<VT_TILES + QT_TILES, 256>>>(value, query, gvT, gqT);

    // 1. all three front GEMMs in one launch (724 CTAs, cp.async pipeline)
    mega_gemm<<<MEGA_CTAS, 256, MEGA_SMEM>>>(gvT, gqT, W_val, b_val, W_off, b_off,
                                             W_attn, b_attn, refp, gv, loc, attn, gmeta);

    // 2. batched branchless gather
    gather_kernel<<<BS * LQ, 256>>>(gv, gmeta, attn, gmid);

    // 3. output projection (2 x 64 = 128 CTAs)
    {
        dim3 grid(EMBED / 128, MQ / 64);
        gemm_out<<<grid, 256>>>(gmid, W_out, b_out, out, MQ, EMBED, EMBED);
    }
}

// round 14
// speedup vs baseline: 1.3480x; 1.0167x over previous
#include <cuda_runtime.h>
#include <cstdint>

// ---------------------------------------------------------------------------
// Problem constants
// ---------------------------------------------------------------------------
#define BS 4
#define LQ 1024
#define EMBED 256
#define NH 8
#define NL 4
#define NP 16
#define HD 32
#define LEN_V 5440
#define MQ (BS * LQ)        // 4096
#define MV (BS * LEN_V)     // 21760

#define OUT_ELEMS   (BS * LQ * EMBED)
#define LOC_OFFSET  (OUT_ELEMS)
#define LOC_ELEMS   (BS * LQ * NH * NL * NP * 2)
#define ATTN_OFFSET (LOC_OFFSET + LOC_ELEMS)

__constant__ int   c_H[NL]      = {64, 32, 16, 8};
__constant__ int   c_W[NL]      = {64, 32, 16, 8};
__constant__ int   c_start[NL]  = {0, 4096, 5120, 5376};
__constant__ float c_invW[NL]   = {1.0f/64, 1.0f/32, 1.0f/16, 1.0f/8};
__constant__ float c_invH[NL]   = {1.0f/64, 1.0f/32, 1.0f/16, 1.0f/8};

__device__ float  g_v[MV * EMBED];                    // projected value ~22.3 MB
__device__ float  g_midT[EMBED * MQ];                 // pre-W_out, k-major  4 MB
__device__ float4 g_meta[MQ * NH * 32 * 4];           // gather meta     ~67 MB
__device__ float  g_vT[EMBED * MV];                   // value transposed 22.3 MB
__device__ float  g_qT[EMBED * MQ];                   // query transposed  4 MB

// ---------------------------------------------------------------------------
// Packed f32x2 + cp.async helpers
// ---------------------------------------------------------------------------
__device__ __forceinline__ uint64_t pack2(float x, float y) {
    uint64_t r;
    asm("mov.b64 %0, {%1, %2};" : "=l"(r) : "f"(x), "f"(y));
    return r;
}
__device__ __forceinline__ void unpack2(uint64_t v, float& x, float& y) {
    asm("mov.b64 {%0, %1}, %2;" : "=f"(x), "=f"(y) : "l"(v));
}
__device__ __forceinline__ void ffma2(uint64_t& d, uint64_t a, uint64_t b) {
    asm("fma.rn.f32x2 %0, %1, %2, %0;" : "+l"(d) : "l"(a), "l"(b));
}
__device__ __forceinline__ void cp16(void* s, const void* g) {
    uint32_t sa = (uint32_t)__cvta_generic_to_shared(s);
    asm volatile("cp.async.ca.shared.global [%0], [%1], 16;" :: "r"(sa), "l"(g));
}
#define CP_COMMIT() asm volatile("cp.async.commit_group;" ::: "memory")
#define CP_WAIT(N)  asm volatile("cp.async.wait_group %0;" :: "n"(N) : "memory")

// ---------------------------------------------------------------------------
// Transpose kernel: value[MV,256] -> vT[256,MV], query[MQ,256] -> qT[256,MQ]
// ---------------------------------------------------------------------------
#define VT_TILES ((MV / 32) * (EMBED / 32))   // 5440
#define QT_TILES ((MQ / 32) * (EMBED / 32))   // 1024

__global__ __launch_bounds__(256) void transpose_kernel(
    const float* __restrict__ value, const float* __restrict__ query,
    float* __restrict__ vT, float* __restrict__ qT)
{
    __shared__ float tile[32][33];
    int t = blockIdx.x;
    const float* src; float* dst; int Mr, tm, tk;
    if (t < VT_TILES) { src = value; dst = vT; Mr = MV; tm = t >> 3; tk = t & 7; }
    else { t -= VT_TILES; src = query; dst = qT; Mr = MQ; tm = t >> 3; tk = t & 7; }

    const int r  = threadIdx.x >> 3;
    const int c4 = threadIdx.x & 7;

    float4 v = *(const float4*)(src + (size_t)(tm * 32 + r) * EMBED + tk * 32 + c4 * 4);
    tile[r][c4 * 4 + 0] = v.x;
    tile[r][c4 * 4 + 1] = v.y;
    tile[r][c4 * 4 + 2] = v.z;
    tile[r][c4 * 4 + 3] = v.w;
    __syncthreads();

    float4 w;
    w.x = tile[c4 * 4 + 0][r];
    w.y = tile[c4 * 4 + 1][r];
    w.z = tile[c4 * 4 + 2][r];
    w.w = tile[c4 * 4 + 3][r];
    *(float4*)(dst + (size_t)(tk * 32 + r) * Mr + tm * 32 + c4 * 4) = w;
}

// ---------------------------------------------------------------------------
// MEGA GEMM with cp.async 3-stage pipeline (unchanged from R13).
// ---------------------------------------------------------------------------
#define TBK  16
#define SAm  128
#define SBm  192
#define STGA (TBK * SAm)               // 2048 floats
#define STGB (TBK * SBm)               // 3072 floats
#define MEGA_SMEM (3 * (STGA + STGB) * 4)   // 61440 B
#define KK   256

#define G3_CTAS 340
#define G1_CTAS 256
#define G2_CTAS 128
#define MEGA_CTAS (G3_CTAS + G1_CTAS + G2_CTAS)

__global__ __launch_bounds__(256, 2) void mega_gemm(
    const float* __restrict__ vT, const float* __restrict__ qT,
    const float* __restrict__ W_val, const float* __restrict__ b_val,
    const float* __restrict__ W_off, const float* __restrict__ b_off,
    const float* __restrict__ W_attn, const float* __restrict__ b_attn,
    const float* __restrict__ refp,
    float* __restrict__ gv, float* __restrict__ loc,
    float* __restrict__ attn_out, float4* __restrict__ meta)
{
    extern __shared__ __align__(16) float smem[];
    float* As = smem;
    float* Bs = smem + 3 * STGA;

    const int cta = blockIdx.x;
    const float *AT, *B, *bias;
    float* C;
    int N, mode, gx, gy, Mlen;
    if (cta < G3_CTAS) {
        AT = vT; Mlen = MV; B = W_val; bias = b_val; C = gv;
        N = 256; mode = 0; gx = cta & 1; gy = cta >> 1;
    } else if (cta < G3_CTAS + G1_CTAS) {
        int l = cta - G3_CTAS;
        AT = qT; Mlen = MQ; B = W_off; bias = b_off; C = loc;
        N = 1024; mode = 1; gx = l & 7; gy = l >> 3;
    } else {
        int l = cta - (G3_CTAS + G1_CTAS);
        AT = qT; Mlen = MQ; B = W_attn; bias = b_attn; C = attn_out;
        N = 512; mode = 2; gx = l & 3; gy = l >> 2;
    }
    const int m0 = gy * 128;
    const int n0 = gx * 128;

    const int tid  = threadIdx.x;
    const int lane = tid & 31;
    const int wid  = tid >> 5;
    const int wm   = wid & 3;
    const int wn   = wid >> 2;
    const int lm   = lane & 3;
    const int ln   = lane >> 2;

    const int aofs = wm * 32 + lm * 8;
    const int bofs = (wn * 8 + ln) * 12;
    const int mb   = wm * 32 + lm * 8;
    const int nb   = wn * 64 + ln * 8;

    auto stage = [&](int sg, int kt) {
        const int k0 = kt * TBK;
#pragma unroll
        for (int r2 = 0; r2 < 2; r2++) {
            int i = tid + r2 * 256;
            int k = i >> 5, m4 = i & 31;
            cp16(As + sg * STGA + k * SAm + m4 * 4,
                 AT + (size_t)(k0 + k) * Mlen + m0 + m4 * 4);
        }
#pragma unroll
        for (int r2 = 0; r2 < 2; r2++) {
            int i = tid + r2 * 256;
            int kk = i >> 5, n4 = i & 31;
            cp16(Bs + sg * STGB + kk * SBm + (n4 >> 1) * 12 + (n4 & 1) * 4,
                 B + (size_t)(k0 + kk) * N + n0 + n4 * 4);
        }
    };

    stage(0, 0); CP_COMMIT();
    stage(1, 1); CP_COMMIT();

    uint64_t acc[8][4];
#pragma unroll
    for (int i = 0; i < 8; i++)
#pragma unroll
        for (int j = 0; j < 4; j++) acc[i][j] = 0ull;

    const int KT = KK / TBK;
    int cur = 0;

#pragma unroll 1
    for (int kt = 0; kt < KT; kt++) {
        if (kt + 1 < KT) { CP_WAIT(1); } else { CP_WAIT(0); }
        __syncthreads();
        if (kt + 2 < KT) {
            int sg = (kt + 2) % 3;
            stage(sg, kt + 2);
            CP_COMMIT();
        }

#pragma unroll
        for (int k = 0; k < TBK; k++) {
            const float* ap = As + cur * STGA + k * SAm + aofs;
            float4 a0 = *(const float4*)(ap);
            float4 a1 = *(const float4*)(ap + 4);
            const uint64_t* bp = (const uint64_t*)(Bs + cur * STGB + k * SBm + bofs);
            uint64_t bd[4];
            bd[0] = bp[0]; bd[1] = bp[1]; bd[2] = bp[2]; bd[3] = bp[3];
            uint64_t ad[8];
            ad[0] = pack2(a0.x, a0.x);
            ad[1] = pack2(a0.y, a0.y);
            ad[2] = pack2(a0.z, a0.z);
            ad[3] = pack2(a0.w, a0.w);
            ad[4] = pack2(a1.x, a1.x);
            ad[5] = pack2(a1.y, a1.y);
            ad[6] = pack2(a1.z, a1.z);
            ad[7] = pack2(a1.w, a1.w);
#pragma unroll
            for (int i = 0; i < 8; i++)
#pragma unroll
                for (int j = 0; j < 4; j++)
                    ffma2(acc[i][j], ad[i], bd[j]);
        }

        cur++;
        if (cur == 3) cur = 0;
    }

    float bn[8];
#pragma unroll
    for (int j = 0; j < 8; j++) bn[j] = __ldg(&bias[n0 + nb + j]);

    float o[8][8];
#pragma unroll
    for (int i = 0; i < 8; i++) {
#pragma unroll
        for (int j = 0; j < 4; j++)
            unpack2(acc[i][j], o[i][2 * j], o[i][2 * j + 1]);
#pragma unroll
        for (int j = 0; j < 8; j++) o[i][j] += bn[j];
    }

    if (mode == 0) {
#pragma unroll
        for (int i = 0; i < 8; i++) {
            float* crow = C + (size_t)(m0 + mb + i) * N + n0 + nb;
            *(float4*)(crow)     = make_float4(o[i][0], o[i][1], o[i][2], o[i][3]);
            *(float4*)(crow + 4) = make_float4(o[i][4], o[i][5], o[i][6], o[i][7]);
        }
    } else if (mode == 1) {
        // ---- sampling-location transform + gather-meta (pair-corner layout) ----
        __syncthreads();
        float* rps = As;
        {
            int row = tid >> 1, half = tid & 1;
            *(float4*)(rps + row * 8 + half * 4) =
                *(const float4*)(refp + (size_t)(m0 + row) * 8 + half * 4);
        }
        __syncthreads();

        const int h = gx;
        const int lvl = wn * 2 + (ln >> 2);
        const int W = c_W[lvl], H = c_H[lvl];
        const float fW = (float)W, fH = (float)H;
        const float invW = c_invW[lvl], invH = c_invH[lvl];
        const int cstE = c_start[lvl] * EMBED;
        const int pbase = (ln & 3) * 4;

#pragma unroll
        for (int i = 0; i < 8; i++) {
            const int bq = m0 + mb + i;
            const float* rp = rps + (mb + i) * 8;
            float rx0 = rp[0], rx1 = rp[1], rx2 = rp[2], rx3 = rp[3];
            float ry0 = rp[4], ry1 = rp[5], ry2 = rp[6], ry3 = rp[7];
            float res[8];
#pragma unroll
            for (int j = 0; j < 8; j++) {
                int p = pbase + (j >> 1);
                int c = j & 1;
                float lam = (float)p * (1.0f / 15.0f);
                float pnt = c ? (((ry0 * lam + ry1) * lam + ry2) * lam + ry3)
                              : (((rx0 * lam + rx1) * lam + rx2) * lam + rx3);
                float inv = c ? invH : invW;
                res[j] = pnt + o[i][j] * inv;
            }
            float* crow = C + (size_t)bq * N + n0 + nb;
            *(float4*)(crow)     = make_float4(res[0], res[1], res[2], res[3]);
            *(float4*)(crow + 4) = make_float4(res[4], res[5], res[6], res[7]);

            float4 cm[4];
            float4* mb4 = meta + ((size_t)(bq * NH + h) * 32 + lvl * 8 + (pbase >> 1)) * 4;
#pragma unroll
            for (int t = 0; t < 4; t++) {
                float x = res[2 * t]     * fW - 0.5f;
                float y = res[2 * t + 1] * fH - 0.5f;
                float x0f = floorf(x);
                float y0f = floorf(y);
                float wx = x - x0f;
                float wy = y - y0f;
                int x0 = (int)x0f, y0 = (int)y0f;
                int x1 = x0 + 1,   y1 = y0 + 1;

                bool vx0 = (x0 >= 0) & (x0 < W);
                bool vx1 = (x1 >= 0) & (x1 < W);
                bool vy0 = (y0 >= 0) & (y0 < H);
                bool vy1 = (y1 >= 0) & (y1 < H);

                float w00 = (vx0 & vy0) ? (1.0f - wx) * (1.0f - wy) : 0.0f;
                float w10 = (vx1 & vy0) ? wx * (1.0f - wy)          : 0.0f;
                float w01 = (vx0 & vy1) ? (1.0f - wx) * wy          : 0.0f;
                float w11 = (vx1 & vy1) ? wx * wy                   : 0.0f;

                int cx0 = min(max(x0, 0), W - 1);
                int cx1 = min(max(x1, 0), W - 1);
                int cy0 = min(max(y0, 0), H - 1);
                int cy1 = min(max(y1, 0), H - 1);

                float i00 = __int_as_float(cstE + (cy0 * W + cx0) * EMBED);
                float i10 = __int_as_float(cstE + (cy0 * W + cx1) * EMBED);
                float i01 = __int_as_float(cstE + (cy1 * W + cx0) * EMBED);
                float i11 = __int_as_float(cstE + (cy1 * W + cx1) * EMBED);

                if ((t & 1) == 0) {
                    cm[0].x = i00; cm[0].y = w00;
                    cm[1].x = i10; cm[1].y = w10;
                    cm[2].x = i01; cm[2].y = w01;
                    cm[3].x = i11; cm[3].y = w11;
                } else {
                    cm[0].z = i00; cm[0].w = w00;
                    cm[1].z = i10; cm[1].w = w10;
                    cm[2].z = i01; cm[2].w = w01;
                    cm[3].z = i11; cm[3].w = w11;
                    int pr = t >> 1;
#pragma unroll
                    for (int c = 0; c < 4; c++)
                        mb4[pr * 4 + c] = cm[c];
                }
            }
        }
    } else {
        // ---- softmax: head block = wn (64 cols), warp-local over ln ----
#pragma unroll
        for (int i = 0; i < 8; i++) {
            float mx = o[i][0];
#pragma unroll
            for (int j = 1; j < 8; j++) mx = fmaxf(mx, o[i][j]);
            mx = fmaxf(mx, __shfl_xor_sync(0xFFFFFFFFu, mx, 4));
            mx = fmaxf(mx, __shfl_xor_sync(0xFFFFFFFFu, mx, 8));
            mx = fmaxf(mx, __shfl_xor_sync(0xFFFFFFFFu, mx, 16));

            float e[8];
            float s = 0.0f;
#pragma unroll
            for (int j = 0; j < 8; j++) { e[j] = expf(o[i][j] - mx); s += e[j]; }
            s += __shfl_xor_sync(0xFFFFFFFFu, s, 4);
            s += __shfl_xor_sync(0xFFFFFFFFu, s, 8);
            s += __shfl_xor_sync(0xFFFFFFFFu, s, 16);
            float inv = 1.0f / s;

            float* crow = C + (size_t)(m0 + mb + i) * N + n0 + nb;
            *(float4*)(crow)     = make_float4(e[0]*inv, e[1]*inv, e[2]*inv, e[3]*inv);
            *(float4*)(crow + 4) = make_float4(e[4]*inv, e[5]*inv, e[6]*inv, e[7]*inv);
        }
    }
}

// ---------------------------------------------------------------------------
// Output projection GEMM, cp.async 3-stage:
//   C[MQ,256] = midT^T[MQ,256] @ W_out[256,256] + b_out
// Tile 64(M) x 128(N) x BK16; 256 thr; microtile 4m x 8n (warp 4m x 2n).
// A is k-major (g_midT) -> contiguous 16B staging. 128 CTAs.
// ---------------------------------------------------------------------------
#define OT_SA   64
#define OT_STGA (TBK * OT_SA)          // 1024 floats
#define OT_STGB (TBK * SBm)            // 3072 floats
#define OT_SMEM (3 * (OT_STGA + OT_STGB) * 4)   // 49152 B

__global__ __launch_bounds__(256, 3) void gemm_out(
    const float* __restrict__ AT,      // [256, MQ]
    const float* __restrict__ B,       // [256, 256]
    const float* __restrict__ bias,
    float* __restrict__ C)             // [MQ, 256]
{
    extern __shared__ __align__(16) float smem[];
    float* As = smem;
    float* Bs = smem + 3 * OT_STGA;

    const int tid  = threadIdx.x;
    const int lane = tid & 31;
    const int wid  = tid >> 5;
    const int wm   = wid & 3;
    const int wn   = wid >> 2;
    const int lm   = lane & 3;
    const int ln   = lane >> 2;
    const int m0   = blockIdx.y * 64;
    const int n0   = blockIdx.x * 128;

    const int aofs = wm * 16 + lm * 4;
    const int bofs = (wn * 8 + ln) * 12;
    const int mb   = aofs;
    const int nb   = wn * 64 + ln * 8;

    auto stage = [&](int sg, int kt) {
        const int k0 = kt * TBK;
        {
            int k = tid >> 4, m4 = tid & 15;
            cp16(As + sg * OT_STGA + k * OT_SA + m4 * 4,
                 AT + (size_t)(k0 + k) * MQ + m0 + m4 * 4);
        }
#pragma unroll
        for (int r2 = 0; r2 < 2; r2++) {
            int i = tid + r2 * 256;
            int kk = i >> 5, n4 = i & 31;
            cp16(Bs + sg * OT_STGB + kk * SBm + (n4 >> 1) * 12 + (n4 & 1) * 4,
                 B + (size_t)(k0 + kk) * 256 + n0 + n4 * 4);
        }
    };

    stage(0, 0); CP_COMMIT();
    stage(1, 1); CP_COMMIT();

    uint64_t acc[4][4];
#pragma unroll
    for (int i = 0; i < 4; i++)
#pragma unroll
        for (int j = 0; j < 4; j++) acc[i][j] = 0ull;

    const int KT = 256 / TBK;   // 16
    int cur = 0;

#pragma unroll 1
    for (int kt = 0; kt < KT; kt++) {
        if (kt + 1 < KT) { CP_WAIT(1); } else { CP_WAIT(0); }
        __syncthreads();
        if (kt + 2 < KT) {
            stage((kt + 2) % 3, kt + 2);
            CP_COMMIT();
        }

#pragma unroll
        for (int k = 0; k < TBK; k++) {
            float4 a4 = *(const float4*)(As + cur * OT_STGA + k * OT_SA + aofs);
            const uint64_t* bp = (const uint64_t*)(Bs + cur * OT_STGB + k * SBm + bofs);
            uint64_t bd[4];
            bd[0] = bp[0]; bd[1] = bp[1]; bd[2] = bp[2]; bd[3] = bp[3];
            uint64_t ad[4];
            ad[0] = pack2(a4.x, a4.x);
            ad[1] = pack2(a4.y, a4.y);
            ad[2] = pack2(a4.z, a4.z);
            ad[3] = pack2(a4.w, a4.w);
#pragma unroll
            for (int i = 0; i < 4; i++)
#pragma unroll
                for (int j = 0; j < 4; j++)
                    ffma2(acc[i][j], ad[i], bd[j]);
        }

        cur++;
        if (cur == 3) cur = 0;
    }

    float bn[8];
#pragma unroll
    for (int j = 0; j < 8; j++) bn[j] = __ldg(&bias[n0 + nb + j]);

#pragma unroll
    for (int i = 0; i < 4; i++) {
        float o[8];
#pragma unroll
        for (int j = 0; j < 4; j++)
            unpack2(acc[i][j], o[2 * j], o[2 * j + 1]);
#pragma unroll
        for (int j = 0; j < 8; j++) o[j] += bn[j];
        float* crow = C + (size_t)(m0 + mb + i) * 256 + n0 + nb;
        *(float4*)(crow)     = make_float4(o[0], o[1], o[2], o[3]);
        *(float4*)(crow + 4) = make_float4(o[4], o[5], o[6], o[7]);
    }
}

// ---------------------------------------------------------------------------
// Gather: warp per (b,q,h); 8-sample batches; writes g_midT (k-major scatter).
// ---------------------------------------------------------------------------
__global__ __launch_bounds__(256) void gather_kernel(
    const float* __restrict__ v,
    const float4* __restrict__ meta,
    const float* __restrict__ attn,
    float* __restrict__ midT)
{
    const int bq = blockIdx.x;
    const int b = bq >> 10;
    const int h = threadIdx.x >> 5;
    const int lane = threadIdx.x & 31;
    const int corner = lane >> 3;
    const int cg = lane & 7;

    const float4* m4p = meta + ((size_t)(bq * NH + h) * 32) * 4 + corner;
    const float*  ah  = attn + ((size_t)bq * NH + h) * 64;
    const float*  vb  = v + (size_t)b * LEN_V * EMBED + h * HD + cg * 4;

    float4 acc = make_float4(0.f, 0.f, 0.f, 0.f);

#pragma unroll
    for (int base = 0; base < 64; base += 8) {
        float4 aA = __ldg((const float4*)(ah + base));
        float4 aB = __ldg((const float4*)(ah + base + 4));
        float4 m4[4];
#pragma unroll
        for (int q = 0; q < 4; q++)
            m4[q] = __ldg(&m4p[(base / 2 + q) * 4]);

        float4 vv[8];
#pragma unroll
        for (int q = 0; q < 4; q++) {
            vv[2 * q]     = *(const float4*)(vb + __float_as_int(m4[q].x));
            vv[2 * q + 1] = *(const float4*)(vb + __float_as_int(m4[q].z));
        }

        float a8[8] = {aA.x, aA.y, aA.z, aA.w, aB.x, aB.y, aB.z, aB.w};
#pragma unroll
        for (int q = 0; q < 4; q++) {
            float w0 = m4[q].y * a8[2 * q];
            float w1 = m4[q].w * a8[2 * q + 1];
            acc.x = fmaf(w0, vv[2 * q].x, acc.x);
            acc.y = fmaf(w0, vv[2 * q].y, acc.y);
            acc.z = fmaf(w0, vv[2 * q].z, acc.z);
            acc.w = fmaf(w0, vv[2 * q].w, acc.w);
            acc.x = fmaf(w1, vv[2 * q + 1].x, acc.x);
            acc.y = fmaf(w1, vv[2 * q + 1].y, acc.y);
            acc.z = fmaf(w1, vv[2 * q + 1].z, acc.z);
            acc.w = fmaf(w1, vv[2 * q + 1].w, acc.w);
        }
    }

#pragma unroll
    for (int off = 8; off <= 16; off <<= 1) {
        acc.x += __shfl_xor_sync(0xFFFFFFFFu, acc.x, off);
        acc.y += __shfl_xor_sync(0xFFFFFFFFu, acc.y, off);
        acc.z += __shfl_xor_sync(0xFFFFFFFFu, acc.z, off);
        acc.w += __shfl_xor_sync(0xFFFFFFFFu, acc.w, off);
    }

    if (lane < 8) {
        // transposed scatter: midT[ch][bq]
        const int ch = h * HD + cg * 4;
        float* col = midT + bq;
        col[(size_t)(ch + 0) * MQ] = acc.x;
        col[(size_t)(ch + 1) * MQ] = acc.y;
        col[(size_t)(ch + 2) * MQ] = acc.z;
        col[(size_t)(ch + 3) * MQ] = acc.w;
    }
}

// ---------------------------------------------------------------------------
// Launch
// ---------------------------------------------------------------------------
extern "C" void kernel_launch(void* const* d_in, const int* in_sizes, int n_in,
                              void* d_out, int out_size)
{
    const float* query  = (const float*)d_in[0];
    const float* refp   = (const float*)d_in[1];
    const float* value  = (const float*)d_in[2];
    const float* W_val  = (const float*)d_in[3];
    const float* b_val  = (const float*)d_in[4];
    const float* W_off  = (const float*)d_in[5];
    const float* b_off  = (const float*)d_in[6];
    const float* W_attn = (const float*)d_in[7];
    const float* b_attn = (const float*)d_in[8];
    const float* W_out  = (const float*)d_in[9];
    const float* b_out  = (const float*)d_in[10];

    float* out  = (float*)d_out;
    float* loc  = out + LOC_OFFSET;
    float* attn = out + ATTN_OFFSET;

    float* gv;
    float* gmidT;
    float4* gmeta;
    float* gvT;
    float* gqT;
    cudaGetSymbolAddress((void**)&gv, g_v);
    cudaGetSymbolAddress((void**)&gmidT, g_midT);
    cudaGetSymbolAddress((void**)&gmeta, g_meta);
    cudaGetSymbolAddress((void**)&gvT, g_vT);
    cudaGetSymbolAddress((void**)&gqT, g_qT);

    cudaFuncSetAttribute(mega_gemm,
                         cudaFuncAttributeMaxDynamicSharedMemorySize, MEGA_SMEM);
    cudaFuncSetAttribute(gemm_out,
                         cudaFuncAttributeMaxDynamicSharedMemorySize, OT_SMEM);

    // 0. one-shot transpose of value + query (k-major A operands)
    transpose_kernel<<<VT_TILES + QT_TILES, 256>>>(value, query, gvT, gqT);

    // 1. all three front GEMMs in one launch (724 CTAs, cp.async pipeline)
    mega_gemm<<<MEGA_CTAS, 256, MEGA_SMEM>>>(gvT, gqT, W_val, b_val, W_off, b_off,
                                             W_attn, b_attn, refp, gv, loc, attn, gmeta);

    // 2. batched branchless gather -> g_midT (transposed)
    gather_kernel<<<BS * LQ, 256>>>(gv, gmeta, attn, gmidT);

    // 3. output projection (2 x 64 = 128 CTAs, cp.async pipeline)
    {
        dim3 grid(EMBED / 128, MQ / 64);
        gemm_out<<<grid, 256, OT_SMEM>>>(gmidT, W_out, b_out, out);
    }
}